// round 10
// baseline (speedup 1.0000x reference)
#include <cuda_runtime.h>
#include <cuda_fp16.h>
#include <math.h>
#include <stdint.h>

#define MTOT 32768
#define LDIM 512

// ---------------- scratch (device globals; allocation-free) ----------------
__device__ __align__(128) float  g_TW[MTOT * 32 * 2];
__device__ __align__(128) __half g_CS[512 * 2048];
__device__ __align__(128) __half g_WINV[2048 * 512];   // cos/sin, NO 2/M scale
__device__ __align__(128) float  g_DL[512 * 512];
__device__ __align__(128) float  g_Q[512 * 512];
__device__ __align__(128) __half g_A1[512 * 512];
__device__ __align__(128) __half g_A2[512 * 512];
__device__ __align__(128) __half g_A3[512 * 512];
__device__ __align__(128) float  g_u1[MTOT];
__device__ __align__(128) float  g_u2[MTOT];
__device__ __align__(128) float  g_u3[MTOT];
__device__ __align__(128) float  g_w1[512];
__device__ __align__(128) float  g_w2[512];
__device__ __align__(128) float  g_w3[512];
__device__ __align__(128) __half g_Yfh[2048 * 16384];  // fold output
__device__ __align__(128) float  g_V[2048 * 16384];    // V (fp32)
__device__ __align__(128) __half g_U[512 * 16384];     // U (fp16)
__device__ __align__(128) __half g_Z2[MTOT * 512];
__device__ __align__(128) __half g_Z3[MTOT * 512];
__device__ __align__(128) __half g_Xr[MTOT * 512];

__device__ __forceinline__ uint32_t f2tf(float x) {
    uint32_t r;
    asm("cvt.rna.tf32.f32 %0, %1;" : "=r"(r) : "f"(x));
    return r;
}

__device__ __forceinline__ uint32_t smem_u32(const void* p) {
    uint32_t a;
    asm("{ .reg .u64 t; cvta.to.shared.u64 t, %1; cvt.u32.u64 %0, t; }" : "=r"(a) : "l"(p));
    return a;
}
__device__ __forceinline__ void cp16s(uint32_t saddr, const void* g) {
    asm volatile("cp.async.cg.shared.global [%0], [%1], 16;" :: "r"(saddr), "l"(g));
}
#define LDSM4(r0, r1, r2, r3, a)                                                   \
    asm volatile("ldmatrix.sync.aligned.m8n8.x4.shared.b16 {%0,%1,%2,%3}, [%4];"   \
                 : "=r"(r0), "=r"(r1), "=r"(r2), "=r"(r3) : "r"(a))
#define LDSM4T(r0, r1, r2, r3, a)                                                  \
    asm volatile("ldmatrix.sync.aligned.m8n8.x4.trans.shared.b16 {%0,%1,%2,%3}, [%4];" \
                 : "=r"(r0), "=r"(r1), "=r"(r2), "=r"(r3) : "r"(a))
#define HMMA(c, a, b)                                                              \
    asm volatile("mma.sync.aligned.m16n8k16.row.col.f32.f16.f16.f32 "              \
                 "{%0,%1,%2,%3}, {%4,%5,%6,%7}, {%8,%9}, {%0,%1,%2,%3};"           \
                 : "+f"((c)[0]), "+f"((c)[1]), "+f"((c)[2]), "+f"((c)[3])          \
                 : "r"((a)[0]), "r"((a)[1]), "r"((a)[2]), "r"((a)[3]),             \
                   "r"((b)[0]), "r"((b)[1]))

// ---------------- table builders ----------------
__global__ void k_build_tw() {
    int id = blockIdx.x * 256 + threadIdx.x;
    if (id >= MTOT * 32) return;
    int n = id >> 5, t = id & 31;
    int mm = ((2 * n + 1) * t) & 131071;
    float sn, cs;
    sincospif((float)mm * (1.0f / 65536.0f), &sn, &cs);
    g_TW[2 * id + 0] = cs;
    g_TW[2 * id + 1] = sn;
}

__global__ void k_build_cs() {
    int id = blockIdx.x * 256 + threadIdx.x;
    if (id >= 512 * 1024) return;
    int j = id >> 10, p = id & 1023;
    int mm = (j * (2 * p + 1)) & 2047;
    float sn, cs;
    sincospif((float)mm * (1.0f / 1024.0f), &sn, &cs);
    g_CS[j * 2048 + p] = __float2half(cs);
    g_CS[j * 2048 + 1024 + p] = __float2half(-sn);
    g_WINV[p * 512 + j] = __float2half(cs);
    g_WINV[(1024 + p) * 512 + j] = __float2half(sn);
}

__global__ void k_build_dl() {
    int id = blockIdx.x * 256 + threadIdx.x;
    if (id >= 512 * 512) return;
    int k = id >> 9, n = id & 511;
    int mm = (k * (2 * n + 1)) & 2047;
    float cs = cospif((float)mm * (1.0f / 1024.0f));
    float ck = (k == 0) ? 0.04419417382415922f : 0.0625f;
    g_DL[id] = ck * cs;
}

struct C2d { double x, y; };
__device__ __forceinline__ C2d cdiv(C2d a, C2d b) {
    double d = b.x * b.x + b.y * b.y;
    C2d r; r.x = (a.x * b.x + a.y * b.y) / d; r.y = (a.y * b.x - a.x * b.y) / d; return r;
}
__device__ __forceinline__ C2d cmul(C2d a, C2d b) {
    C2d r; r.x = a.x * b.x - a.y * b.y; r.y = a.x * b.y + a.y * b.x; return r;
}
__global__ void k_build_u() {
    int n = blockIdx.x * 256 + threadIdx.x;
    if (n >= MTOT) return;
    long on = 2L * n + 1;
    double s1, c1, s64, c64, s32, c32, s16, c16;
    sincospi((double)on / 65536.0, &s1, &c1);
    sincospi((double)(on & 2047) / 1024.0, &s64, &c64);
    sincospi((double)(on & 4095) / 2048.0, &s32, &c32);
    sincospi((double)(on & 8191) / 4096.0, &s16, &c16);
    C2d numer; numer.x = 1.0; numer.y = (n & 1) ? 1.0 : -1.0;
    C2d d1;  d1.x  = 1.0 - c1;  d1.y  = -s1;
    C2d d64; d64.x = 1.0 - c64; d64.y = -s64;
    C2d n32; n32.x = 1.0 - c32; n32.y = -s32;
    C2d n16; n16.x = 1.0 - c16; n16.y = -s16;
    double F1 = cdiv(numer, d1).x;
    C2d g = cdiv(numer, d64);
    double F2 = cmul(g, cdiv(n32, d1)).x;
    double F3 = cmul(g, cdiv(n16, d1)).x;
    const double C2M = 0.0078125;
    const double C1M = 0.005524271728019903;
    g_u1[n] = (float)(C2M * (F1 - 1.0) + C1M);
    g_u2[n] = (float)(C2M * (F2 - 1.0) + C1M);
    g_u3[n] = (float)(C2M * (F3 - 1.0) + C1M);
}

__global__ void k_build_w(int Kb, const float* __restrict__ b, float* __restrict__ w) {
    int c = blockIdx.x * 128 + threadIdx.x;
    if (c >= 512) return;
    float s = 0.f;
    for (int k = 0; k < Kb; k++) s += g_DL[k * 512 + c] * b[k];
    w[c] = s;
}

// ---------------- fold: X -> Yfh (fp16) + Xr (fp16) ----------------
__global__ void __launch_bounds__(128) k_fold(const float* __restrict__ X) {
    const int p = blockIdx.y;
    const int l = blockIdx.x * 128 + threadIdx.x;
    __shared__ float tw[32][64];
    for (int i = threadIdx.x; i < 2048; i += 128) {
        int q = i >> 6;
        tw[q][i & 63] = g_TW[(((long)(q << 10) + p)) * 64 + (i & 63)];
    }
    __syncthreads();
    float c[32], s[32];
#pragma unroll
    for (int t = 0; t < 32; t++) { c[t] = 0.f; s[t] = 0.f; }
    for (int q = 0; q < 32; q++) {
        int n = (q << 10) + p;
        float x = X[(long)n * 512 + l];
        g_Xr[(long)n * 512 + l] = __float2half(x);
#pragma unroll
        for (int t = 0; t < 32; t++) {
            c[t] += tw[q][2 * t] * x;
            s[t] += tw[q][2 * t + 1] * x;
        }
    }
#pragma unroll
    for (int t = 0; t < 32; t++) {
        g_Yfh[(long)p * 16384 + t * 512 + l] = __float2half(c[t]);
        g_Yfh[(long)(1024 + p) * 16384 + t * 512 + l] = __float2half(s[t]);
    }
}

// halve k=0 entries: U row j=0, first 512 cols (t=0)
__global__ void k_fixup() {
    int l = blockIdx.x * 128 + threadIdx.x;
    if (l < 512) g_U[l] = __float2half(__half2float(g_U[l]) * 0.5f);
}

// ---------------- combine: V -> Z3 (t<16), Z2 (t<32); applies 2/M ----------------
__global__ void __launch_bounds__(128) k_combine(const float* __restrict__ V) {
    const int p = blockIdx.y;
    const int l = blockIdx.x * 128 + threadIdx.x;
    __shared__ float tw[32][64];
    for (int i = threadIdx.x; i < 2048; i += 128) {
        int q = i >> 6;
        tw[q][i & 63] = g_TW[(((long)(q << 10) + p)) * 64 + (i & 63)];
    }
    __syncthreads();
    float vc[32], vs[32];
#pragma unroll
    for (int t = 0; t < 32; t++) {
        vc[t] = V[(long)p * 16384 + t * 512 + l];
        vs[t] = V[(long)(1024 + p) * 16384 + t * 512 + l];
    }
    const float SC = 2.0f / 32768.0f;
    for (int q = 0; q < 32; q++) {
        float acc = 0.f;
#pragma unroll
        for (int t = 0; t < 16; t++) acc += tw[q][2 * t] * vc[t] - tw[q][2 * t + 1] * vs[t];
        int n = (q << 10) + p;
        g_Z3[(long)n * 512 + l] = __float2half(acc * SC);
#pragma unroll
        for (int t = 16; t < 32; t++) acc += tw[q][2 * t] * vc[t] - tw[q][2 * t + 1] * vs[t];
        g_Z2[(long)n * 512 + l] = __float2half(acc * SC);
    }
}

// ---------------- small tf32 mma.sync GEMM (builder matrices) ----------------
__global__ void __launch_bounds__(256) k_mma(
    const float* __restrict__ A, const float* __restrict__ B, void* __restrict__ Cv,
    int M, int N, int K, int lda, int ldb, int ldc, int transA, int halfOut) {
    __shared__ uint32_t As[16][132];
    __shared__ uint32_t Bs[16][132];
    const int tid = threadIdx.x;
    const int wid = tid >> 5, lane = tid & 31;
    const int wm = wid & 1, wn = wid >> 1;
    const int g = lane >> 2, t4 = lane & 3;
    const int m0 = blockIdx.y * 128, n0 = blockIdx.x * 128;
    float acc[4][4][4];
#pragma unroll
    for (int i = 0; i < 4; i++)
#pragma unroll
        for (int j = 0; j < 4; j++)
#pragma unroll
            for (int r = 0; r < 4; r++) acc[i][j][r] = 0.f;
    const int bk = tid >> 4, bn = (tid & 15) * 8;
    const int ar = tid >> 1, ak = (tid & 1) * 8;
    for (int k0 = 0; k0 < K; k0 += 16) {
        const float* Ap;
        if (transA) Ap = A + (long)(k0 + bk) * lda + m0 + bn;
        else        Ap = A + (long)(m0 + ar) * lda + k0 + ak;
        float4 pa0 = *(const float4*)(Ap);
        float4 pa1 = *(const float4*)(Ap + 4);
        const float* Bp = B + (long)(k0 + bk) * ldb + n0 + bn;
        float4 pb0 = *(const float4*)(Bp);
        float4 pb1 = *(const float4*)(Bp + 4);
        if (transA) {
            uint4 v0, v1;
            v0.x = f2tf(pa0.x); v0.y = f2tf(pa0.y); v0.z = f2tf(pa0.z); v0.w = f2tf(pa0.w);
            v1.x = f2tf(pa1.x); v1.y = f2tf(pa1.y); v1.z = f2tf(pa1.z); v1.w = f2tf(pa1.w);
            *(uint4*)&As[bk][bn] = v0;
            *(uint4*)&As[bk][bn + 4] = v1;
        } else {
            As[ak + 0][ar] = f2tf(pa0.x);
            As[ak + 1][ar] = f2tf(pa0.y);
            As[ak + 2][ar] = f2tf(pa0.z);
            As[ak + 3][ar] = f2tf(pa0.w);
            As[ak + 4][ar] = f2tf(pa1.x);
            As[ak + 5][ar] = f2tf(pa1.y);
            As[ak + 6][ar] = f2tf(pa1.z);
            As[ak + 7][ar] = f2tf(pa1.w);
        }
        {
            uint4 v0, v1;
            v0.x = f2tf(pb0.x); v0.y = f2tf(pb0.y); v0.z = f2tf(pb0.z); v0.w = f2tf(pb0.w);
            v1.x = f2tf(pb1.x); v1.y = f2tf(pb1.y); v1.z = f2tf(pb1.z); v1.w = f2tf(pb1.w);
            *(uint4*)&Bs[bk][bn] = v0;
            *(uint4*)&Bs[bk][bn + 4] = v1;
        }
        __syncthreads();
#pragma unroll
        for (int ks = 0; ks < 2; ks++) {
            const int kb = ks * 8;
            uint32_t a[4][4], b[4][2];
#pragma unroll
            for (int mi = 0; mi < 4; mi++) {
                int row = wm * 64 + mi * 16 + g;
                a[mi][0] = As[kb + t4][row];
                a[mi][1] = As[kb + t4][row + 8];
                a[mi][2] = As[kb + t4 + 4][row];
                a[mi][3] = As[kb + t4 + 4][row + 8];
            }
#pragma unroll
            for (int nj = 0; nj < 4; nj++) {
                int col = wn * 32 + nj * 8 + g;
                b[nj][0] = Bs[kb + t4][col];
                b[nj][1] = Bs[kb + t4 + 4][col];
            }
#pragma unroll
            for (int mi = 0; mi < 4; mi++)
#pragma unroll
                for (int nj = 0; nj < 4; nj++) {
                    asm("mma.sync.aligned.m16n8k8.row.col.f32.tf32.tf32.f32 "
                        "{%0,%1,%2,%3}, {%4,%5,%6,%7}, {%8,%9}, {%0,%1,%2,%3};"
                        : "+f"(acc[mi][nj][0]), "+f"(acc[mi][nj][1]),
                          "+f"(acc[mi][nj][2]), "+f"(acc[mi][nj][3])
                        : "r"(a[mi][0]), "r"(a[mi][1]), "r"(a[mi][2]), "r"(a[mi][3]),
                          "r"(b[nj][0]), "r"(b[nj][1]));
                }
        }
        __syncthreads();
    }
#pragma unroll
    for (int mi = 0; mi < 4; mi++) {
        int r = wm * 64 + mi * 16 + g;
#pragma unroll
        for (int nj = 0; nj < 4; nj++) {
            int c = wn * 32 + nj * 8 + t4 * 2;
            if (halfOut) {
                __half* Ch = (__half*)Cv;
                __half2 h0, h1;
                h0.x = __float2half(acc[mi][nj][0]); h0.y = __float2half(acc[mi][nj][1]);
                h1.x = __float2half(acc[mi][nj][2]); h1.y = __float2half(acc[mi][nj][3]);
                *(__half2*)(Ch + (long)(m0 + r) * ldc + n0 + c) = h0;
                *(__half2*)(Ch + (long)(m0 + r + 8) * ldc + n0 + c) = h1;
            } else {
                float* C = (float*)Cv;
                float2 v0, v1;
                v0.x = acc[mi][nj][0]; v0.y = acc[mi][nj][1];
                v1.x = acc[mi][nj][2]; v1.y = acc[mi][nj][3];
                *(float2*)(C + (long)(m0 + r) * ldc + n0 + c) = v0;
                *(float2*)(C + (long)(m0 + r + 8) * ldc + n0 + c) = v1;
            }
        }
    }
}

// ---------------- pipelined fp16 GEMM, 128x256 tile, warp 64x64 ----------------
// C[M,N] = A[M,K]*B[K,N] (+ u w^T). BK=32 halves, 3-stage cp.async, 256 threads.
#define SA_STRIDE 40     // halves per A row (80B, conflict-free ldsm)
#define SB_STRIDE 264    // halves per B row (528B, conflict-free ldsm: 16*r mod 128 distinct)
#define SA_BYTES (128 * SA_STRIDE * 2)   // 10240
#define SB_BYTES (32 * SB_STRIDE * 2)    // 16896
#define H_STAGE (SA_BYTES + SB_BYTES)    // 27136
#define H_NSTG 3
#define H_SMEM (H_NSTG * H_STAGE)        // 81408

__global__ void __launch_bounds__(256, 1) k_hgemm(
    const __half* __restrict__ A, const __half* __restrict__ B, void* __restrict__ Cv,
    int K, int lda, int ldb, int ldc,
    const float* __restrict__ u, const float* __restrict__ w, int halfOut, int mswap) {
    extern __shared__ __align__(16) char hs[];
    const uint32_t base = smem_u32(hs);
    const int tid = threadIdx.x;
    const int wid = tid >> 5, lane = tid & 31;
    const int wm = wid & 1, wn = wid >> 1;          // 2 x 4 warps, warp tile 64x64
    const int g = lane >> 2, t4 = lane & 3;
    const int bm = mswap ? blockIdx.x : blockIdx.y;
    const int bn = mswap ? blockIdx.y : blockIdx.x;
    const int m0 = bm * 128;
    const long n0 = (long)bn * 256;
    const int KT = K >> 5;

    const int arow = tid >> 2, acol = (tid & 3) * 8;   // A: rows +0,+64
    const int brow = tid >> 5, bcol = (tid & 31) * 8;  // B: k-rows +0,+8,+16,+24

    float acc[4][8][4];
#pragma unroll
    for (int i = 0; i < 4; i++)
#pragma unroll
        for (int j = 0; j < 8; j++)
#pragma unroll
            for (int r = 0; r < 4; r++) acc[i][j][r] = 0.f;

#define H_ISSUE(st, kt) do {                                                       \
        uint32_t _a = base + (st) * H_STAGE;                                       \
        uint32_t _b = _a + SA_BYTES;                                               \
        long _k = (long)(kt) << 5;                                                 \
        cp16s(_a + (arow * SA_STRIDE + acol) * 2,                                  \
              A + (long)(m0 + arow) * lda + _k + acol);                            \
        cp16s(_a + ((arow + 64) * SA_STRIDE + acol) * 2,                           \
              A + (long)(m0 + arow + 64) * lda + _k + acol);                       \
        cp16s(_b + (brow * SB_STRIDE + bcol) * 2,                                  \
              B + (_k + brow) * ldb + n0 + bcol);                                  \
        cp16s(_b + ((brow + 8) * SB_STRIDE + bcol) * 2,                            \
              B + (_k + brow + 8) * ldb + n0 + bcol);                              \
        cp16s(_b + ((brow + 16) * SB_STRIDE + bcol) * 2,                           \
              B + (_k + brow + 16) * ldb + n0 + bcol);                             \
        cp16s(_b + ((brow + 24) * SB_STRIDE + bcol) * 2,                           \
              B + (_k + brow + 24) * ldb + n0 + bcol);                             \
        asm volatile("cp.async.commit_group;");                                    \
    } while (0)

    H_ISSUE(0, 0);
    if (KT > 1) H_ISSUE(1, 1);
    int put = 2, cur = 0;

    for (int kt = 0; kt < KT; kt++) {
        asm volatile("cp.async.wait_group %0;" :: "n"(1));
        __syncthreads();
        int nt = kt + 2;
        if (nt < KT) {
            H_ISSUE(put, nt);
            if (++put == H_NSTG) put = 0;
        }
        const uint32_t sa = base + cur * H_STAGE;
        const uint32_t sb = sa + SA_BYTES;
        if (++cur == H_NSTG) cur = 0;
#pragma unroll
        for (int ks = 0; ks < 2; ks++) {
            uint32_t a[4][4], b[8][2];
#pragma unroll
            for (int mi = 0; mi < 4; mi++) {
                uint32_t ad = sa + (((wm * 64 + mi * 16 + (lane & 15)) * SA_STRIDE)
                                    + ks * 16 + (lane >> 4) * 8) * 2;
                LDSM4(a[mi][0], a[mi][1], a[mi][2], a[mi][3], ad);
            }
#pragma unroll
            for (int njp = 0; njp < 4; njp++) {
                uint32_t bd = sb + (((ks * 16 + (lane & 15)) * SB_STRIDE)
                                    + wn * 64 + njp * 16 + (lane >> 4) * 8) * 2;
                uint32_t r0, r1, r2, r3;
                LDSM4T(r0, r1, r2, r3, bd);
                b[2 * njp][0] = r0; b[2 * njp][1] = r1;
                b[2 * njp + 1][0] = r2; b[2 * njp + 1][1] = r3;
            }
#pragma unroll
            for (int mi = 0; mi < 4; mi++)
#pragma unroll
                for (int nj = 0; nj < 8; nj++)
                    HMMA(acc[mi][nj], a[mi], b[nj]);
        }
        __syncthreads();
    }

    const bool r1 = (u != nullptr);
#pragma unroll
    for (int mi = 0; mi < 4; mi++) {
        int r = wm * 64 + mi * 16 + g;
        float u0 = 0.f, u1 = 0.f;
        if (r1) { u0 = u[m0 + r]; u1 = u[m0 + r + 8]; }
#pragma unroll
        for (int nj = 0; nj < 8; nj++) {
            long c = wn * 64 + nj * 8 + t4 * 2;
            float w0 = 0.f, w1 = 0.f;
            if (r1) { w0 = w[n0 + c]; w1 = w[n0 + c + 1]; }
            float v00 = acc[mi][nj][0] + u0 * w0;
            float v01 = acc[mi][nj][1] + u0 * w1;
            float v10 = acc[mi][nj][2] + u1 * w0;
            float v11 = acc[mi][nj][3] + u1 * w1;
            if (halfOut) {
                __half* Ch = (__half*)Cv;
                __half2 h0, h1;
                h0.x = __float2half(v00); h0.y = __float2half(v01);
                h1.x = __float2half(v10); h1.y = __float2half(v11);
                *(__half2*)(Ch + (long)(m0 + r) * ldc + n0 + c) = h0;
                *(__half2*)(Ch + (long)(m0 + r + 8) * ldc + n0 + c) = h1;
            } else {
                float* C = (float*)Cv;
                float2 f0, f1;
                f0.x = v00; f0.y = v01;
                f1.x = v10; f1.y = v11;
                *(float2*)(C + (long)(m0 + r) * ldc + n0 + c) = f0;
                *(float2*)(C + (long)(m0 + r + 8) * ldc + n0 + c) = f1;
            }
        }
    }
}

// ---------------- launch ----------------
extern "C" void kernel_launch(void* const* d_in, const int* in_sizes, int n_in,
                              void* d_out, int out_size) {
    const float* X  = (const float*)d_in[0];
    const float* W1 = (const float*)d_in[1];
    const float* b1 = (const float*)d_in[2];
    const float* W2 = (const float*)d_in[3];
    const float* b2 = (const float*)d_in[4];
    const float* W3 = (const float*)d_in[5];
    const float* b3 = (const float*)d_in[6];
    float* out = (float*)d_out;

    __half *pCS, *pWINV, *pA1, *pA2, *pA3, *pYfh, *pU, *pZ2, *pZ3, *pXr;
    float *pDL, *pQ, *pu1, *pu2, *pu3, *pw1, *pw2, *pw3, *pV;
    cudaGetSymbolAddress((void**)&pCS, g_CS);
    cudaGetSymbolAddress((void**)&pWINV, g_WINV);
    cudaGetSymbolAddress((void**)&pDL, g_DL);
    cudaGetSymbolAddress((void**)&pQ, g_Q);
    cudaGetSymbolAddress((void**)&pA1, g_A1);
    cudaGetSymbolAddress((void**)&pA2, g_A2);
    cudaGetSymbolAddress((void**)&pA3, g_A3);
    cudaGetSymbolAddress((void**)&pu1, g_u1);
    cudaGetSymbolAddress((void**)&pu2, g_u2);
    cudaGetSymbolAddress((void**)&pu3, g_u3);
    cudaGetSymbolAddress((void**)&pw1, g_w1);
    cudaGetSymbolAddress((void**)&pw2, g_w2);
    cudaGetSymbolAddress((void**)&pw3, g_w3);
    cudaGetSymbolAddress((void**)&pYfh, g_Yfh);
    cudaGetSymbolAddress((void**)&pV, g_V);
    cudaGetSymbolAddress((void**)&pU, g_U);
    cudaGetSymbolAddress((void**)&pZ2, g_Z2);
    cudaGetSymbolAddress((void**)&pZ3, g_Z3);
    cudaGetSymbolAddress((void**)&pXr, g_Xr);

    cudaFuncSetAttribute(k_hgemm, cudaFuncAttributeMaxDynamicSharedMemorySize, H_SMEM);

    k_build_tw<<<(MTOT * 32) / 256, 256>>>();
    k_build_cs<<<(512 * 1024) / 256, 256>>>();
    k_build_dl<<<(512 * 512) / 256, 256>>>();
    k_build_u<<<MTOT / 256, 256>>>();
    k_fold<<<dim3(4, 1024), 128>>>(X);

    // U = CS[512x2048] @ Yfh[2048x16384] -> half.  mswap=1: blocks sharing a B
    // n-tile (4 m's) are schedule-adjacent -> L2 dedups the 67MB Yfh stream.
    k_hgemm<<<dim3(4, 64), 256, H_SMEM>>>(pCS, pYfh, pU, 2048,
                                          2048, 16384, 16384, nullptr, nullptr, 1, 1);
    k_fixup<<<4, 128>>>();
    k_build_w<<<4, 128>>>(512, b1, pw1);
    k_build_w<<<4, 128>>>(256, b2, pw2);
    k_build_w<<<4, 128>>>(128, b3, pw3);

    // builders (tf32): Q = Wk @ DL[0:Kk]; Ak = Q^T @ DL  (half out)
    k_mma<<<dim3(4, 4), 256>>>(W1, pDL, pQ, 512, 512, 512, 512, 512, 512, 0, 0);
    k_mma<<<dim3(4, 4), 256>>>(pQ, pDL, pA1, 512, 512, 512, 512, 512, 512, 1, 1);
    k_mma<<<dim3(4, 2), 256>>>(W2, pDL, pQ, 256, 512, 256, 256, 512, 512, 0, 0);
    k_mma<<<dim3(4, 4), 256>>>(pQ, pDL, pA2, 512, 512, 256, 512, 512, 512, 1, 1);
    k_mma<<<dim3(4, 1), 256>>>(W3, pDL, pQ, 128, 512, 128, 128, 512, 512, 0, 0);
    k_mma<<<dim3(4, 4), 256>>>(pQ, pDL, pA3, 512, 512, 128, 512, 512, 512, 1, 1);

    // V = WINV[2048x512] @ U[512x16384] -> fp32 (U is L2-resident)
    k_hgemm<<<dim3(16, 64), 256, H_SMEM>>>(pWINV, pU, pV, 512,
                                           512, 16384, 16384, nullptr, nullptr, 0, 1);
    k_combine<<<dim3(4, 1024), 128>>>(pV);

    // outputs (mswap=0: 2 n-blocks sharing each A m-tile are adjacent)
    k_hgemm<<<dim3(2, 256), 256, H_SMEM>>>(pXr, pA1, out,        512,
                                           512, 512, 1536, pu1, pw1, 0, 0);
    k_hgemm<<<dim3(2, 256), 256, H_SMEM>>>(pZ2, pA2, out + 512,  512,
                                           512, 512, 1536, pu2, pw2, 0, 0);
    k_hgemm<<<dim3(2, 256), 256, H_SMEM>>>(pZ3, pA3, out + 1024, 512,
                                           512, 512, 1536, pu3, pw3, 0, 0);
    (void)in_sizes; (void)n_in; (void)out_size;
}

// round 15
// speedup vs baseline: 1.0764x; 1.0764x over previous
#include <cuda_runtime.h>
#include <cuda_fp16.h>
#include <math.h>
#include <stdint.h>

#define MTOT 32768
#define LDIM 512

// ---------------- scratch (device globals; allocation-free) ----------------
__device__ __align__(128) float  g_TW[MTOT * 32 * 2];
__device__ __align__(128) __half g_CS[512 * 2048];
__device__ __align__(128) __half g_WINV[2048 * 512];   // cos/sin, NO 2/M scale
__device__ __align__(128) float  g_DL[512 * 512];
__device__ __align__(128) float  g_Q[512 * 512];
__device__ __align__(128) __half g_A1[512 * 512];
__device__ __align__(128) __half g_A2[512 * 512];
__device__ __align__(128) __half g_A3[512 * 512];
__device__ __align__(128) float  g_u1[MTOT];
__device__ __align__(128) float  g_u2[MTOT];
__device__ __align__(128) float  g_u3[MTOT];
__device__ __align__(128) float  g_w1[512];
__device__ __align__(128) float  g_w2[512];
__device__ __align__(128) float  g_w3[512];
__device__ __align__(128) __half g_Yfh[2048 * 16384];  // fold output
__device__ __align__(128) float  g_V[2048 * 16384];    // V (fp32)
__device__ __align__(128) __half g_U[512 * 16384];     // U (fp16)
__device__ __align__(128) __half g_Z2[MTOT * 512];
__device__ __align__(128) __half g_Z3[MTOT * 512];
__device__ __align__(128) __half g_Xr[MTOT * 512];

__device__ __forceinline__ uint32_t f2tf(float x) {
    uint32_t r;
    asm("cvt.rna.tf32.f32 %0, %1;" : "=r"(r) : "f"(x));
    return r;
}

__device__ __forceinline__ uint32_t smem_u32(const void* p) {
    uint32_t a;
    asm("{ .reg .u64 t; cvta.to.shared.u64 t, %1; cvt.u32.u64 %0, t; }" : "=r"(a) : "l"(p));
    return a;
}
__device__ __forceinline__ void cp16s(uint32_t saddr, const void* g) {
    asm volatile("cp.async.cg.shared.global [%0], [%1], 16;" :: "r"(saddr), "l"(g));
}
#define LDSM4(r0, r1, r2, r3, a)                                                   \
    asm volatile("ldmatrix.sync.aligned.m8n8.x4.shared.b16 {%0,%1,%2,%3}, [%4];"   \
                 : "=r"(r0), "=r"(r1), "=r"(r2), "=r"(r3) : "r"(a))
#define LDSM4T(r0, r1, r2, r3, a)                                                  \
    asm volatile("ldmatrix.sync.aligned.m8n8.x4.trans.shared.b16 {%0,%1,%2,%3}, [%4];" \
                 : "=r"(r0), "=r"(r1), "=r"(r2), "=r"(r3) : "r"(a))
#define HMMA(c, a, b)                                                              \
    asm volatile("mma.sync.aligned.m16n8k16.row.col.f32.f16.f16.f32 "              \
                 "{%0,%1,%2,%3}, {%4,%5,%6,%7}, {%8,%9}, {%0,%1,%2,%3};"           \
                 : "+f"((c)[0]), "+f"((c)[1]), "+f"((c)[2]), "+f"((c)[3])          \
                 : "r"((a)[0]), "r"((a)[1]), "r"((a)[2]), "r"((a)[3]),             \
                   "r"((b)[0]), "r"((b)[1]))

// ---------------- table builders ----------------
__global__ void k_build_tw() {
    int id = blockIdx.x * 256 + threadIdx.x;
    if (id >= MTOT * 32) return;
    int n = id >> 5, t = id & 31;
    int mm = ((2 * n + 1) * t) & 131071;
    float sn, cs;
    sincospif((float)mm * (1.0f / 65536.0f), &sn, &cs);
    g_TW[2 * id + 0] = cs;
    g_TW[2 * id + 1] = sn;
}

__global__ void k_build_cs() {
    int id = blockIdx.x * 256 + threadIdx.x;
    if (id >= 512 * 1024) return;
    int j = id >> 10, p = id & 1023;
    int mm = (j * (2 * p + 1)) & 2047;
    float sn, cs;
    sincospif((float)mm * (1.0f / 1024.0f), &sn, &cs);
    g_CS[j * 2048 + p] = __float2half(cs);
    g_CS[j * 2048 + 1024 + p] = __float2half(-sn);
    g_WINV[p * 512 + j] = __float2half(cs);
    g_WINV[(1024 + p) * 512 + j] = __float2half(sn);
}

__global__ void k_build_dl() {
    int id = blockIdx.x * 256 + threadIdx.x;
    if (id >= 512 * 512) return;
    int k = id >> 9, n = id & 511;
    int mm = (k * (2 * n + 1)) & 2047;
    float cs = cospif((float)mm * (1.0f / 1024.0f));
    float ck = (k == 0) ? 0.04419417382415922f : 0.0625f;
    g_DL[id] = ck * cs;
}

struct C2d { double x, y; };
__device__ __forceinline__ C2d cdiv(C2d a, C2d b) {
    double d = b.x * b.x + b.y * b.y;
    C2d r; r.x = (a.x * b.x + a.y * b.y) / d; r.y = (a.y * b.x - a.x * b.y) / d; return r;
}
__device__ __forceinline__ C2d cmul(C2d a, C2d b) {
    C2d r; r.x = a.x * b.x - a.y * b.y; r.y = a.x * b.y + a.y * b.x; return r;
}
__global__ void k_build_u() {
    int n = blockIdx.x * 256 + threadIdx.x;
    if (n >= MTOT) return;
    long on = 2L * n + 1;
    double s1, c1, s64, c64, s32, c32, s16, c16;
    sincospi((double)on / 65536.0, &s1, &c1);
    sincospi((double)(on & 2047) / 1024.0, &s64, &c64);
    sincospi((double)(on & 4095) / 2048.0, &s32, &c32);
    sincospi((double)(on & 8191) / 4096.0, &s16, &c16);
    C2d numer; numer.x = 1.0; numer.y = (n & 1) ? 1.0 : -1.0;
    C2d d1;  d1.x  = 1.0 - c1;  d1.y  = -s1;
    C2d d64; d64.x = 1.0 - c64; d64.y = -s64;
    C2d n32; n32.x = 1.0 - c32; n32.y = -s32;
    C2d n16; n16.x = 1.0 - c16; n16.y = -s16;
    double F1 = cdiv(numer, d1).x;
    C2d g = cdiv(numer, d64);
    double F2 = cmul(g, cdiv(n32, d1)).x;
    double F3 = cmul(g, cdiv(n16, d1)).x;
    const double C2M = 0.0078125;
    const double C1M = 0.005524271728019903;
    g_u1[n] = (float)(C2M * (F1 - 1.0) + C1M);
    g_u2[n] = (float)(C2M * (F2 - 1.0) + C1M);
    g_u3[n] = (float)(C2M * (F3 - 1.0) + C1M);
}

__global__ void k_build_w(int Kb, const float* __restrict__ b, float* __restrict__ w) {
    int c = blockIdx.x * 128 + threadIdx.x;
    if (c >= 512) return;
    float s = 0.f;
    for (int k = 0; k < Kb; k++) s += g_DL[k * 512 + c] * b[k];
    w[c] = s;
}

// ---------------- fold: X -> Yfh (fp16) + Xr (fp16) ----------------
__global__ void __launch_bounds__(128) k_fold(const float* __restrict__ X) {
    const int p = blockIdx.y;
    const int l = blockIdx.x * 128 + threadIdx.x;
    __shared__ float tw[32][64];
    for (int i = threadIdx.x; i < 2048; i += 128) {
        int q = i >> 6;
        tw[q][i & 63] = g_TW[(((long)(q << 10) + p)) * 64 + (i & 63)];
    }
    __syncthreads();
    float c[32], s[32];
#pragma unroll
    for (int t = 0; t < 32; t++) { c[t] = 0.f; s[t] = 0.f; }
    for (int q = 0; q < 32; q++) {
        int n = (q << 10) + p;
        float x = X[(long)n * 512 + l];
        g_Xr[(long)n * 512 + l] = __float2half(x);
#pragma unroll
        for (int t = 0; t < 32; t++) {
            c[t] += tw[q][2 * t] * x;
            s[t] += tw[q][2 * t + 1] * x;
        }
    }
#pragma unroll
    for (int t = 0; t < 32; t++) {
        g_Yfh[(long)p * 16384 + t * 512 + l] = __float2half(c[t]);
        g_Yfh[(long)(1024 + p) * 16384 + t * 512 + l] = __float2half(s[t]);
    }
}

// halve k=0 entries: U row j=0, first 512 cols (t=0)
__global__ void k_fixup() {
    int l = blockIdx.x * 128 + threadIdx.x;
    if (l < 512) g_U[l] = __float2half(__half2float(g_U[l]) * 0.5f);
}

// ---------------- combine: V -> Z3 (t<16), Z2 (t<32); applies 2/M ----------------
__global__ void __launch_bounds__(128) k_combine(const float* __restrict__ V) {
    const int p = blockIdx.y;
    const int l = blockIdx.x * 128 + threadIdx.x;
    __shared__ float tw[32][64];
    for (int i = threadIdx.x; i < 2048; i += 128) {
        int q = i >> 6;
        tw[q][i & 63] = g_TW[(((long)(q << 10) + p)) * 64 + (i & 63)];
    }
    __syncthreads();
    float vc[32], vs[32];
#pragma unroll
    for (int t = 0; t < 32; t++) {
        vc[t] = V[(long)p * 16384 + t * 512 + l];
        vs[t] = V[(long)(1024 + p) * 16384 + t * 512 + l];
    }
    const float SC = 2.0f / 32768.0f;
    for (int q = 0; q < 32; q++) {
        float acc = 0.f;
#pragma unroll
        for (int t = 0; t < 16; t++) acc += tw[q][2 * t] * vc[t] - tw[q][2 * t + 1] * vs[t];
        int n = (q << 10) + p;
        g_Z3[(long)n * 512 + l] = __float2half(acc * SC);
#pragma unroll
        for (int t = 16; t < 32; t++) acc += tw[q][2 * t] * vc[t] - tw[q][2 * t + 1] * vs[t];
        g_Z2[(long)n * 512 + l] = __float2half(acc * SC);
    }
}

// ---------------- small tf32 mma.sync GEMM (builder matrices) ----------------
__global__ void __launch_bounds__(256) k_mma(
    const float* __restrict__ A, const float* __restrict__ B, void* __restrict__ Cv,
    int M, int N, int K, int lda, int ldb, int ldc, int transA, int halfOut) {
    __shared__ uint32_t As[16][132];
    __shared__ uint32_t Bs[16][132];
    const int tid = threadIdx.x;
    const int wid = tid >> 5, lane = tid & 31;
    const int wm = wid & 1, wn = wid >> 1;
    const int g = lane >> 2, t4 = lane & 3;
    const int m0 = blockIdx.y * 128, n0 = blockIdx.x * 128;
    float acc[4][4][4];
#pragma unroll
    for (int i = 0; i < 4; i++)
#pragma unroll
        for (int j = 0; j < 4; j++)
#pragma unroll
            for (int r = 0; r < 4; r++) acc[i][j][r] = 0.f;
    const int bk = tid >> 4, bn = (tid & 15) * 8;
    const int ar = tid >> 1, ak = (tid & 1) * 8;
    for (int k0 = 0; k0 < K; k0 += 16) {
        const float* Ap;
        if (transA) Ap = A + (long)(k0 + bk) * lda + m0 + bn;
        else        Ap = A + (long)(m0 + ar) * lda + k0 + ak;
        float4 pa0 = *(const float4*)(Ap);
        float4 pa1 = *(const float4*)(Ap + 4);
        const float* Bp = B + (long)(k0 + bk) * ldb + n0 + bn;
        float4 pb0 = *(const float4*)(Bp);
        float4 pb1 = *(const float4*)(Bp + 4);
        if (transA) {
            uint4 v0, v1;
            v0.x = f2tf(pa0.x); v0.y = f2tf(pa0.y); v0.z = f2tf(pa0.z); v0.w = f2tf(pa0.w);
            v1.x = f2tf(pa1.x); v1.y = f2tf(pa1.y); v1.z = f2tf(pa1.z); v1.w = f2tf(pa1.w);
            *(uint4*)&As[bk][bn] = v0;
            *(uint4*)&As[bk][bn + 4] = v1;
        } else {
            As[ak + 0][ar] = f2tf(pa0.x);
            As[ak + 1][ar] = f2tf(pa0.y);
            As[ak + 2][ar] = f2tf(pa0.z);
            As[ak + 3][ar] = f2tf(pa0.w);
            As[ak + 4][ar] = f2tf(pa1.x);
            As[ak + 5][ar] = f2tf(pa1.y);
            As[ak + 6][ar] = f2tf(pa1.z);
            As[ak + 7][ar] = f2tf(pa1.w);
        }
        {
            uint4 v0, v1;
            v0.x = f2tf(pb0.x); v0.y = f2tf(pb0.y); v0.z = f2tf(pb0.z); v0.w = f2tf(pb0.w);
            v1.x = f2tf(pb1.x); v1.y = f2tf(pb1.y); v1.z = f2tf(pb1.z); v1.w = f2tf(pb1.w);
            *(uint4*)&Bs[bk][bn] = v0;
            *(uint4*)&Bs[bk][bn + 4] = v1;
        }
        __syncthreads();
#pragma unroll
        for (int ks = 0; ks < 2; ks++) {
            const int kb = ks * 8;
            uint32_t a[4][4], b[4][2];
#pragma unroll
            for (int mi = 0; mi < 4; mi++) {
                int row = wm * 64 + mi * 16 + g;
                a[mi][0] = As[kb + t4][row];
                a[mi][1] = As[kb + t4][row + 8];
                a[mi][2] = As[kb + t4 + 4][row];
                a[mi][3] = As[kb + t4 + 4][row + 8];
            }
#pragma unroll
            for (int nj = 0; nj < 4; nj++) {
                int col = wn * 32 + nj * 8 + g;
                b[nj][0] = Bs[kb + t4][col];
                b[nj][1] = Bs[kb + t4 + 4][col];
            }
#pragma unroll
            for (int mi = 0; mi < 4; mi++)
#pragma unroll
                for (int nj = 0; nj < 4; nj++) {
                    asm("mma.sync.aligned.m16n8k8.row.col.f32.tf32.tf32.f32 "
                        "{%0,%1,%2,%3}, {%4,%5,%6,%7}, {%8,%9}, {%0,%1,%2,%3};"
                        : "+f"(acc[mi][nj][0]), "+f"(acc[mi][nj][1]),
                          "+f"(acc[mi][nj][2]), "+f"(acc[mi][nj][3])
                        : "r"(a[mi][0]), "r"(a[mi][1]), "r"(a[mi][2]), "r"(a[mi][3]),
                          "r"(b[nj][0]), "r"(b[nj][1]));
                }
        }
        __syncthreads();
    }
#pragma unroll
    for (int mi = 0; mi < 4; mi++) {
        int r = wm * 64 + mi * 16 + g;
#pragma unroll
        for (int nj = 0; nj < 4; nj++) {
            int c = wn * 32 + nj * 8 + t4 * 2;
            if (halfOut) {
                __half* Ch = (__half*)Cv;
                __half2 h0, h1;
                h0.x = __float2half(acc[mi][nj][0]); h0.y = __float2half(acc[mi][nj][1]);
                h1.x = __float2half(acc[mi][nj][2]); h1.y = __float2half(acc[mi][nj][3]);
                *(__half2*)(Ch + (long)(m0 + r) * ldc + n0 + c) = h0;
                *(__half2*)(Ch + (long)(m0 + r + 8) * ldc + n0 + c) = h1;
            } else {
                float* C = (float*)Cv;
                float2 v0, v1;
                v0.x = acc[mi][nj][0]; v0.y = acc[mi][nj][1];
                v1.x = acc[mi][nj][2]; v1.y = acc[mi][nj][3];
                *(float2*)(C + (long)(m0 + r) * ldc + n0 + c) = v0;
                *(float2*)(C + (long)(m0 + r + 8) * ldc + n0 + c) = v1;
            }
        }
    }
}

// ---------------- pipelined fp16 GEMM (LDSM + HMMA), 128x128, warp 64x32 ----------------
// C[M,N] = A[M,K]*B[K,N] (+ u w^T). BK=32 halves, 5-stage cp.async, 1 sync/slab.
#define SA_STRIDE 40     // halves per A row (80B, conflict-free ldsm)
#define SB_STRIDE 136    // halves per B row (272B)
#define SA_BYTES (128 * SA_STRIDE * 2)   // 10240
#define SB_BYTES (32 * SB_STRIDE * 2)    // 8704
#define H_STAGE (SA_BYTES + SB_BYTES)    // 18944
#define H_NSTG 5
#define H_SMEM (H_NSTG * H_STAGE)        // 94720

__global__ void __launch_bounds__(256, 2) k_hgemm(
    const __half* __restrict__ A, const __half* __restrict__ B, void* __restrict__ Cv,
    int K, int lda, int ldb, int ldc,
    const float* __restrict__ u, const float* __restrict__ w, int halfOut, int mswap) {
    extern __shared__ __align__(16) char hs[];
    const uint32_t base = smem_u32(hs);
    const int tid = threadIdx.x;
    const int wid = tid >> 5, lane = tid & 31;
    const int wm = wid & 1, wn = wid >> 1;
    const int g = lane >> 2, t4 = lane & 3;
    const int bm = mswap ? blockIdx.x : blockIdx.y;
    const int bn = mswap ? blockIdx.y : blockIdx.x;
    const int m0 = bm * 128;
    const long n0 = (long)bn * 128;
    const int KT = K >> 5;

    const int arow = tid >> 2, acol = (tid & 3) * 8;   // A: 2 chunks (rows +0,+64)
    const int brow = tid >> 4, bcol = (tid & 15) * 8;  // B: 2 chunks (k +0,+16)

    float acc[4][4][4];
#pragma unroll
    for (int i = 0; i < 4; i++)
#pragma unroll
        for (int j = 0; j < 4; j++)
#pragma unroll
            for (int r = 0; r < 4; r++) acc[i][j][r] = 0.f;

#define H_ISSUE(st, kt) do {                                                       \
        uint32_t _a = base + (st) * H_STAGE;                                       \
        uint32_t _b = _a + SA_BYTES;                                               \
        long _k = (long)(kt) << 5;                                                 \
        cp16s(_a + (arow * SA_STRIDE + acol) * 2,                                  \
              A + (long)(m0 + arow) * lda + _k + acol);                            \
        cp16s(_a + ((arow + 64) * SA_STRIDE + acol) * 2,                           \
              A + (long)(m0 + arow + 64) * lda + _k + acol);                       \
        cp16s(_b + (brow * SB_STRIDE + bcol) * 2,                                  \
              B + (_k + brow) * ldb + n0 + bcol);                                  \
        cp16s(_b + ((brow + 16) * SB_STRIDE + bcol) * 2,                           \
              B + (_k + brow + 16) * ldb + n0 + bcol);                             \
        asm volatile("cp.async.commit_group;");                                    \
    } while (0)

    // prologue: fill 4 of 5 stages
#pragma unroll
    for (int s = 0; s < H_NSTG - 1; s++)
        if (s < KT) H_ISSUE(s, s);
    int put = H_NSTG - 1, cur = 0;

    for (int kt = 0; kt < KT; kt++) {
        asm volatile("cp.async.wait_group %0;" :: "n"(H_NSTG - 2));
        __syncthreads();      // orders: (a) slab kt visible, (b) all warps done with buffer 'put'
        int nt = kt + H_NSTG - 1;
        if (nt < KT) {
            H_ISSUE(put, nt);
            if (++put == H_NSTG) put = 0;
        }
        const uint32_t sa = base + cur * H_STAGE;
        const uint32_t sb = sa + SA_BYTES;
        if (++cur == H_NSTG) cur = 0;
#pragma unroll
        for (int ks = 0; ks < 2; ks++) {
            uint32_t a[4][4], b[4][2];
#pragma unroll
            for (int mi = 0; mi < 4; mi++) {
                uint32_t ad = sa + (((wm * 64 + mi * 16 + (lane & 15)) * SA_STRIDE)
                                    + ks * 16 + (lane >> 4) * 8) * 2;
                LDSM4(a[mi][0], a[mi][1], a[mi][2], a[mi][3], ad);
            }
#pragma unroll
            for (int njp = 0; njp < 2; njp++) {
                uint32_t bd = sb + (((ks * 16 + (lane & 15)) * SB_STRIDE)
                                    + wn * 32 + njp * 16 + (lane >> 4) * 8) * 2;
                uint32_t r0, r1, r2, r3;
                LDSM4T(r0, r1, r2, r3, bd);
                b[2 * njp][0] = r0; b[2 * njp][1] = r1;
                b[2 * njp + 1][0] = r2; b[2 * njp + 1][1] = r3;
            }
#pragma unroll
            for (int mi = 0; mi < 4; mi++)
#pragma unroll
                for (int nj = 0; nj < 4; nj++)
                    HMMA(acc[mi][nj], a[mi], b[nj]);
        }
        // no trailing __syncthreads: next iteration's leading sync orders buffer reuse
    }

    const bool r1 = (u != nullptr);
#pragma unroll
    for (int mi = 0; mi < 4; mi++) {
        int r = wm * 64 + mi * 16 + g;
        float u0 = 0.f, u1 = 0.f;
        if (r1) { u0 = u[m0 + r]; u1 = u[m0 + r + 8]; }
#pragma unroll
        for (int nj = 0; nj < 4; nj++) {
            long c = wn * 32 + nj * 8 + t4 * 2;
            float w0 = 0.f, w1 = 0.f;
            if (r1) { w0 = w[n0 + c]; w1 = w[n0 + c + 1]; }
            float v00 = acc[mi][nj][0] + u0 * w0;
            float v01 = acc[mi][nj][1] + u0 * w1;
            float v10 = acc[mi][nj][2] + u1 * w0;
            float v11 = acc[mi][nj][3] + u1 * w1;
            if (halfOut) {
                __half* Ch = (__half*)Cv;
                __half2 h0, h1;
                h0.x = __float2half(v00); h0.y = __float2half(v01);
                h1.x = __float2half(v10); h1.y = __float2half(v11);
                *(__half2*)(Ch + (long)(m0 + r) * ldc + n0 + c) = h0;
                *(__half2*)(Ch + (long)(m0 + r + 8) * ldc + n0 + c) = h1;
            } else {
                float* C = (float*)Cv;
                float2 f0, f1;
                f0.x = v00; f0.y = v01;
                f1.x = v10; f1.y = v11;
                *(float2*)(C + (long)(m0 + r) * ldc + n0 + c) = f0;
                *(float2*)(C + (long)(m0 + r + 8) * ldc + n0 + c) = f1;
            }
        }
    }
}

// ---------------- launch ----------------
extern "C" void kernel_launch(void* const* d_in, const int* in_sizes, int n_in,
                              void* d_out, int out_size) {
    const float* X  = (const float*)d_in[0];
    const float* W1 = (const float*)d_in[1];
    const float* b1 = (const float*)d_in[2];
    const float* W2 = (const float*)d_in[3];
    const float* b2 = (const float*)d_in[4];
    const float* W3 = (const float*)d_in[5];
    const float* b3 = (const float*)d_in[6];
    float* out = (float*)d_out;

    __half *pCS, *pWINV, *pA1, *pA2, *pA3, *pYfh, *pU, *pZ2, *pZ3, *pXr;
    float *pDL, *pQ, *pu1, *pu2, *pu3, *pw1, *pw2, *pw3, *pV;
    cudaGetSymbolAddress((void**)&pCS, g_CS);
    cudaGetSymbolAddress((void**)&pWINV, g_WINV);
    cudaGetSymbolAddress((void**)&pDL, g_DL);
    cudaGetSymbolAddress((void**)&pQ, g_Q);
    cudaGetSymbolAddress((void**)&pA1, g_A1);
    cudaGetSymbolAddress((void**)&pA2, g_A2);
    cudaGetSymbolAddress((void**)&pA3, g_A3);
    cudaGetSymbolAddress((void**)&pu1, g_u1);
    cudaGetSymbolAddress((void**)&pu2, g_u2);
    cudaGetSymbolAddress((void**)&pu3, g_u3);
    cudaGetSymbolAddress((void**)&pw1, g_w1);
    cudaGetSymbolAddress((void**)&pw2, g_w2);
    cudaGetSymbolAddress((void**)&pw3, g_w3);
    cudaGetSymbolAddress((void**)&pYfh, g_Yfh);
    cudaGetSymbolAddress((void**)&pV, g_V);
    cudaGetSymbolAddress((void**)&pU, g_U);
    cudaGetSymbolAddress((void**)&pZ2, g_Z2);
    cudaGetSymbolAddress((void**)&pZ3, g_Z3);
    cudaGetSymbolAddress((void**)&pXr, g_Xr);

    cudaFuncSetAttribute(k_hgemm, cudaFuncAttributeMaxDynamicSharedMemorySize, H_SMEM);

    k_build_tw<<<(MTOT * 32) / 256, 256>>>();
    k_build_cs<<<(512 * 1024) / 256, 256>>>();
    k_build_dl<<<(512 * 512) / 256, 256>>>();
    k_build_u<<<MTOT / 256, 256>>>();
    k_fold<<<dim3(4, 1024), 128>>>(X);

    // U = CS[512x2048] @ Yfh[2048x16384] -> half.  mswap=1: the 4 m-blocks that
    // share each Yfh n-tile are schedule-adjacent -> L2 dedups the B stream.
    k_hgemm<<<dim3(4, 128), 256, H_SMEM>>>(pCS, pYfh, pU, 2048,
                                           2048, 16384, 16384, nullptr, nullptr, 1, 1);
    k_fixup<<<4, 128>>>();
    k_build_w<<<4, 128>>>(512, b1, pw1);
    k_build_w<<<4, 128>>>(256, b2, pw2);
    k_build_w<<<4, 128>>>(128, b3, pw3);

    // builders (tf32): Q = Wk @ DL[0:Kk]; Ak = Q^T @ DL  (half out)
    k_mma<<<dim3(4, 4), 256>>>(W1, pDL, pQ, 512, 512, 512, 512, 512, 512, 0, 0);
    k_mma<<<dim3(4, 4), 256>>>(pQ, pDL, pA1, 512, 512, 512, 512, 512, 512, 1, 1);
    k_mma<<<dim3(4, 2), 256>>>(W2, pDL, pQ, 256, 512, 256, 256, 512, 512, 0, 0);
    k_mma<<<dim3(4, 4), 256>>>(pQ, pDL, pA2, 512, 512, 256, 512, 512, 512, 1, 1);
    k_mma<<<dim3(4, 1), 256>>>(W3, pDL, pQ, 128, 512, 128, 128, 512, 512, 0, 0);
    k_mma<<<dim3(4, 4), 256>>>(pQ, pDL, pA3, 512, 512, 128, 512, 512, 512, 1, 1);

    // V = WINV[2048x512] @ U[512x16384] -> fp32 (U is L2-resident)
    k_hgemm<<<dim3(128, 16), 256, H_SMEM>>>(pWINV, pU, pV, 512,
                                            512, 16384, 16384, nullptr, nullptr, 0, 0);
    k_combine<<<dim3(4, 1024), 128>>>(pV);

    // outputs
    k_hgemm<<<dim3(4, 256), 256, H_SMEM>>>(pXr, pA1, out,        512,
                                           512, 512, 1536, pu1, pw1, 0, 0);
    k_hgemm<<<dim3(4, 256), 256, H_SMEM>>>(pZ2, pA2, out + 512,  512,
                                           512, 512, 1536, pu2, pw2, 0, 0);
    k_hgemm<<<dim3(4, 256), 256, H_SMEM>>>(pZ3, pA3, out + 1024, 512,
                                           512, 512, 1536, pu3, pw3, 0, 0);
    (void)in_sizes; (void)n_in; (void)out_size;
}

// round 16
// speedup vs baseline: 1.1512x; 1.0695x over previous
#include <cuda_runtime.h>
#include <cuda_fp16.h>
#include <math.h>
#include <stdint.h>

#define MTOT 32768
#define LDIM 512

// ---------------- scratch (device globals; allocation-free) ----------------
__device__ __align__(128) float  g_TW[MTOT * 32 * 2];
__device__ __align__(128) __half g_CS[512 * 2048];
__device__ __align__(128) __half g_WINV[2048 * 512];   // cos/sin, NO 2/M scale
__device__ __align__(128) float  g_DL[512 * 512];
__device__ __align__(128) float  g_Q[512 * 512];
__device__ __align__(128) __half g_A1[512 * 512];
__device__ __align__(128) __half g_A2[512 * 512];
__device__ __align__(128) __half g_A3[512 * 512];
__device__ __align__(128) float  g_u1[MTOT];
__device__ __align__(128) float  g_u2[MTOT];
__device__ __align__(128) float  g_u3[MTOT];
__device__ __align__(128) float  g_w1[512];
__device__ __align__(128) float  g_w2[512];
__device__ __align__(128) float  g_w3[512];
__device__ __align__(128) __half g_Yfh[2048 * 16384];  // fold output; REUSED as V (fp16)
__device__ __align__(128) __half g_U[512 * 16384];     // U (fp16)
__device__ __align__(128) __half g_Z2[MTOT * 512];
__device__ __align__(128) __half g_Z3[MTOT * 512];
__device__ __align__(128) __half g_Xr[MTOT * 512];

__device__ __forceinline__ uint32_t f2tf(float x) {
    uint32_t r;
    asm("cvt.rna.tf32.f32 %0, %1;" : "=r"(r) : "f"(x));
    return r;
}

__device__ __forceinline__ uint32_t smem_u32(const void* p) {
    uint32_t a;
    asm("{ .reg .u64 t; cvta.to.shared.u64 t, %1; cvt.u32.u64 %0, t; }" : "=r"(a) : "l"(p));
    return a;
}
__device__ __forceinline__ void cp16s(uint32_t saddr, const void* g) {
    asm volatile("cp.async.cg.shared.global [%0], [%1], 16;" :: "r"(saddr), "l"(g));
}
#define LDSM4(r0, r1, r2, r3, a)                                                   \
    asm volatile("ldmatrix.sync.aligned.m8n8.x4.shared.b16 {%0,%1,%2,%3}, [%4];"   \
                 : "=r"(r0), "=r"(r1), "=r"(r2), "=r"(r3) : "r"(a))
#define LDSM4T(r0, r1, r2, r3, a)                                                  \
    asm volatile("ldmatrix.sync.aligned.m8n8.x4.trans.shared.b16 {%0,%1,%2,%3}, [%4];" \
                 : "=r"(r0), "=r"(r1), "=r"(r2), "=r"(r3) : "r"(a))
#define HMMA(c, a, b)                                                              \
    asm volatile("mma.sync.aligned.m16n8k16.row.col.f32.f16.f16.f32 "              \
                 "{%0,%1,%2,%3}, {%4,%5,%6,%7}, {%8,%9}, {%0,%1,%2,%3};"           \
                 : "+f"((c)[0]), "+f"((c)[1]), "+f"((c)[2]), "+f"((c)[3])          \
                 : "r"((a)[0]), "r"((a)[1]), "r"((a)[2]), "r"((a)[3]),             \
                   "r"((b)[0]), "r"((b)[1]))

// ---------------- table builders ----------------
__global__ void k_build_tw() {
    int id = blockIdx.x * 256 + threadIdx.x;
    if (id >= MTOT * 32) return;
    int n = id >> 5, t = id & 31;
    int mm = ((2 * n + 1) * t) & 131071;
    float sn, cs;
    sincospif((float)mm * (1.0f / 65536.0f), &sn, &cs);
    g_TW[2 * id + 0] = cs;
    g_TW[2 * id + 1] = sn;
}

__global__ void k_build_cs() {
    int id = blockIdx.x * 256 + threadIdx.x;
    if (id >= 512 * 1024) return;
    int j = id >> 10, p = id & 1023;
    int mm = (j * (2 * p + 1)) & 2047;
    float sn, cs;
    sincospif((float)mm * (1.0f / 1024.0f), &sn, &cs);
    g_CS[j * 2048 + p] = __float2half(cs);
    g_CS[j * 2048 + 1024 + p] = __float2half(-sn);
    g_WINV[p * 512 + j] = __float2half(cs);
    g_WINV[(1024 + p) * 512 + j] = __float2half(sn);
}

__global__ void k_build_dl() {
    int id = blockIdx.x * 256 + threadIdx.x;
    if (id >= 512 * 512) return;
    int k = id >> 9, n = id & 511;
    int mm = (k * (2 * n + 1)) & 2047;
    float cs = cospif((float)mm * (1.0f / 1024.0f));
    float ck = (k == 0) ? 0.04419417382415922f : 0.0625f;
    g_DL[id] = ck * cs;
}

struct C2d { double x, y; };
__device__ __forceinline__ C2d cdiv(C2d a, C2d b) {
    double d = b.x * b.x + b.y * b.y;
    C2d r; r.x = (a.x * b.x + a.y * b.y) / d; r.y = (a.y * b.x - a.x * b.y) / d; return r;
}
__device__ __forceinline__ C2d cmul(C2d a, C2d b) {
    C2d r; r.x = a.x * b.x - a.y * b.y; r.y = a.x * b.y + a.y * b.x; return r;
}
__global__ void k_build_u() {
    int n = blockIdx.x * 256 + threadIdx.x;
    if (n >= MTOT) return;
    long on = 2L * n + 1;
    double s1, c1, s64, c64, s32, c32, s16, c16;
    sincospi((double)on / 65536.0, &s1, &c1);
    sincospi((double)(on & 2047) / 1024.0, &s64, &c64);
    sincospi((double)(on & 4095) / 2048.0, &s32, &c32);
    sincospi((double)(on & 8191) / 4096.0, &s16, &c16);
    C2d numer; numer.x = 1.0; numer.y = (n & 1) ? 1.0 : -1.0;
    C2d d1;  d1.x  = 1.0 - c1;  d1.y  = -s1;
    C2d d64; d64.x = 1.0 - c64; d64.y = -s64;
    C2d n32; n32.x = 1.0 - c32; n32.y = -s32;
    C2d n16; n16.x = 1.0 - c16; n16.y = -s16;
    double F1 = cdiv(numer, d1).x;
    C2d g = cdiv(numer, d64);
    double F2 = cmul(g, cdiv(n32, d1)).x;
    double F3 = cmul(g, cdiv(n16, d1)).x;
    const double C2M = 0.0078125;
    const double C1M = 0.005524271728019903;
    g_u1[n] = (float)(C2M * (F1 - 1.0) + C1M);
    g_u2[n] = (float)(C2M * (F2 - 1.0) + C1M);
    g_u3[n] = (float)(C2M * (F3 - 1.0) + C1M);
}

__global__ void k_build_w(int Kb, const float* __restrict__ b, float* __restrict__ w) {
    int c = blockIdx.x * 128 + threadIdx.x;
    if (c >= 512) return;
    float s = 0.f;
    for (int k = 0; k < Kb; k++) s += g_DL[k * 512 + c] * b[k];
    w[c] = s;
}

// ---------------- fold: X -> Yfh (fp16) + Xr (fp16) ----------------
__global__ void __launch_bounds__(128) k_fold(const float* __restrict__ X) {
    const int p = blockIdx.y;
    const int l = blockIdx.x * 128 + threadIdx.x;
    __shared__ float tw[32][64];
    for (int i = threadIdx.x; i < 2048; i += 128) {
        int q = i >> 6;
        tw[q][i & 63] = g_TW[(((long)(q << 10) + p)) * 64 + (i & 63)];
    }
    __syncthreads();
    float c[32], s[32];
#pragma unroll
    for (int t = 0; t < 32; t++) { c[t] = 0.f; s[t] = 0.f; }
    for (int q = 0; q < 32; q++) {
        int n = (q << 10) + p;
        float x = X[(long)n * 512 + l];
        g_Xr[(long)n * 512 + l] = __float2half(x);
#pragma unroll
        for (int t = 0; t < 32; t++) {
            c[t] += tw[q][2 * t] * x;
            s[t] += tw[q][2 * t + 1] * x;
        }
    }
#pragma unroll
    for (int t = 0; t < 32; t++) {
        g_Yfh[(long)p * 16384 + t * 512 + l] = __float2half(c[t]);
        g_Yfh[(long)(1024 + p) * 16384 + t * 512 + l] = __float2half(s[t]);
    }
}

// halve k=0 entries: U row j=0, first 512 cols (t=0)
__global__ void k_fixup() {
    int l = blockIdx.x * 128 + threadIdx.x;
    if (l < 512) g_U[l] = __float2half(__half2float(g_U[l]) * 0.5f);
}

// ---------------- combine: V (fp16) -> Z3 (t<16), Z2 (t<32); applies 2/M ----------------
__global__ void __launch_bounds__(128) k_combine(const __half* __restrict__ V) {
    const int p = blockIdx.y;
    const int l = blockIdx.x * 128 + threadIdx.x;
    __shared__ float tw[32][64];
    for (int i = threadIdx.x; i < 2048; i += 128) {
        int q = i >> 6;
        tw[q][i & 63] = g_TW[(((long)(q << 10) + p)) * 64 + (i & 63)];
    }
    __syncthreads();
    float vc[32], vs[32];
#pragma unroll
    for (int t = 0; t < 32; t++) {
        vc[t] = __half2float(V[(long)p * 16384 + t * 512 + l]);
        vs[t] = __half2float(V[(long)(1024 + p) * 16384 + t * 512 + l]);
    }
    const float SC = 2.0f / 32768.0f;
    for (int q = 0; q < 32; q++) {
        float acc = 0.f;
#pragma unroll
        for (int t = 0; t < 16; t++) acc += tw[q][2 * t] * vc[t] - tw[q][2 * t + 1] * vs[t];
        int n = (q << 10) + p;
        g_Z3[(long)n * 512 + l] = __float2half(acc * SC);
#pragma unroll
        for (int t = 16; t < 32; t++) acc += tw[q][2 * t] * vc[t] - tw[q][2 * t + 1] * vs[t];
        g_Z2[(long)n * 512 + l] = __float2half(acc * SC);
    }
}

// ---------------- small tf32 mma.sync GEMM (builder matrices) ----------------
__global__ void __launch_bounds__(256) k_mma(
    const float* __restrict__ A, const float* __restrict__ B, void* __restrict__ Cv,
    int M, int N, int K, int lda, int ldb, int ldc, int transA, int halfOut) {
    __shared__ uint32_t As[16][132];
    __shared__ uint32_t Bs[16][132];
    const int tid = threadIdx.x;
    const int wid = tid >> 5, lane = tid & 31;
    const int wm = wid & 1, wn = wid >> 1;
    const int g = lane >> 2, t4 = lane & 3;
    const int m0 = blockIdx.y * 128, n0 = blockIdx.x * 128;
    float acc[4][4][4];
#pragma unroll
    for (int i = 0; i < 4; i++)
#pragma unroll
        for (int j = 0; j < 4; j++)
#pragma unroll
            for (int r = 0; r < 4; r++) acc[i][j][r] = 0.f;
    const int bk = tid >> 4, bn = (tid & 15) * 8;
    const int ar = tid >> 1, ak = (tid & 1) * 8;
    for (int k0 = 0; k0 < K; k0 += 16) {
        const float* Ap;
        if (transA) Ap = A + (long)(k0 + bk) * lda + m0 + bn;
        else        Ap = A + (long)(m0 + ar) * lda + k0 + ak;
        float4 pa0 = *(const float4*)(Ap);
        float4 pa1 = *(const float4*)(Ap + 4);
        const float* Bp = B + (long)(k0 + bk) * ldb + n0 + bn;
        float4 pb0 = *(const float4*)(Bp);
        float4 pb1 = *(const float4*)(Bp + 4);
        if (transA) {
            uint4 v0, v1;
            v0.x = f2tf(pa0.x); v0.y = f2tf(pa0.y); v0.z = f2tf(pa0.z); v0.w = f2tf(pa0.w);
            v1.x = f2tf(pa1.x); v1.y = f2tf(pa1.y); v1.z = f2tf(pa1.z); v1.w = f2tf(pa1.w);
            *(uint4*)&As[bk][bn] = v0;
            *(uint4*)&As[bk][bn + 4] = v1;
        } else {
            As[ak + 0][ar] = f2tf(pa0.x);
            As[ak + 1][ar] = f2tf(pa0.y);
            As[ak + 2][ar] = f2tf(pa0.z);
            As[ak + 3][ar] = f2tf(pa0.w);
            As[ak + 4][ar] = f2tf(pa1.x);
            As[ak + 5][ar] = f2tf(pa1.y);
            As[ak + 6][ar] = f2tf(pa1.z);
            As[ak + 7][ar] = f2tf(pa1.w);
        }
        {
            uint4 v0, v1;
            v0.x = f2tf(pb0.x); v0.y = f2tf(pb0.y); v0.z = f2tf(pb0.z); v0.w = f2tf(pb0.w);
            v1.x = f2tf(pb1.x); v1.y = f2tf(pb1.y); v1.z = f2tf(pb1.z); v1.w = f2tf(pb1.w);
            *(uint4*)&Bs[bk][bn] = v0;
            *(uint4*)&Bs[bk][bn + 4] = v1;
        }
        __syncthreads();
#pragma unroll
        for (int ks = 0; ks < 2; ks++) {
            const int kb = ks * 8;
            uint32_t a[4][4], b[4][2];
#pragma unroll
            for (int mi = 0; mi < 4; mi++) {
                int row = wm * 64 + mi * 16 + g;
                a[mi][0] = As[kb + t4][row];
                a[mi][1] = As[kb + t4][row + 8];
                a[mi][2] = As[kb + t4 + 4][row];
                a[mi][3] = As[kb + t4 + 4][row + 8];
            }
#pragma unroll
            for (int nj = 0; nj < 4; nj++) {
                int col = wn * 32 + nj * 8 + g;
                b[nj][0] = Bs[kb + t4][col];
                b[nj][1] = Bs[kb + t4 + 4][col];
            }
#pragma unroll
            for (int mi = 0; mi < 4; mi++)
#pragma unroll
                for (int nj = 0; nj < 4; nj++) {
                    asm("mma.sync.aligned.m16n8k8.row.col.f32.tf32.tf32.f32 "
                        "{%0,%1,%2,%3}, {%4,%5,%6,%7}, {%8,%9}, {%0,%1,%2,%3};"
                        : "+f"(acc[mi][nj][0]), "+f"(acc[mi][nj][1]),
                          "+f"(acc[mi][nj][2]), "+f"(acc[mi][nj][3])
                        : "r"(a[mi][0]), "r"(a[mi][1]), "r"(a[mi][2]), "r"(a[mi][3]),
                          "r"(b[nj][0]), "r"(b[nj][1]));
                }
        }
        __syncthreads();
    }
#pragma unroll
    for (int mi = 0; mi < 4; mi++) {
        int r = wm * 64 + mi * 16 + g;
#pragma unroll
        for (int nj = 0; nj < 4; nj++) {
            int c = wn * 32 + nj * 8 + t4 * 2;
            if (halfOut) {
                __half* Ch = (__half*)Cv;
                __half2 h0, h1;
                h0.x = __float2half(acc[mi][nj][0]); h0.y = __float2half(acc[mi][nj][1]);
                h1.x = __float2half(acc[mi][nj][2]); h1.y = __float2half(acc[mi][nj][3]);
                *(__half2*)(Ch + (long)(m0 + r) * ldc + n0 + c) = h0;
                *(__half2*)(Ch + (long)(m0 + r + 8) * ldc + n0 + c) = h1;
            } else {
                float* C = (float*)Cv;
                float2 v0, v1;
                v0.x = acc[mi][nj][0]; v0.y = acc[mi][nj][1];
                v1.x = acc[mi][nj][2]; v1.y = acc[mi][nj][3];
                *(float2*)(C + (long)(m0 + r) * ldc + n0 + c) = v0;
                *(float2*)(C + (long)(m0 + r + 8) * ldc + n0 + c) = v1;
            }
        }
    }
}

// ---------------- pipelined fp16 GEMM (LDSM + HMMA), 128x128, warp 64x32 ----------------
#define SA_STRIDE 40     // halves per A row (80B, conflict-free ldsm)
#define SB_STRIDE 136    // halves per B row (272B)
#define SA_BYTES (128 * SA_STRIDE * 2)   // 10240
#define SB_BYTES (32 * SB_STRIDE * 2)    // 8704
#define H_STAGE (SA_BYTES + SB_BYTES)    // 18944
#define H_NSTG 5
#define H_SMEM (H_NSTG * H_STAGE)        // 94720

// shared k-loop body between k_hgemm and k_hgemm3
#define H_ISSUE_BODY(st, kt, Aop, Bop, ldA, ldB) do {                              \
        uint32_t _a = base + (st) * H_STAGE;                                       \
        uint32_t _b = _a + SA_BYTES;                                               \
        long _k = (long)(kt) << 5;                                                 \
        cp16s(_a + (arow * SA_STRIDE + acol) * 2,                                  \
              (Aop) + (long)(m0 + arow) * (ldA) + _k + acol);                      \
        cp16s(_a + ((arow + 64) * SA_STRIDE + acol) * 2,                           \
              (Aop) + (long)(m0 + arow + 64) * (ldA) + _k + acol);                 \
        cp16s(_b + (brow * SB_STRIDE + bcol) * 2,                                  \
              (Bop) + (_k + brow) * (ldB) + n0 + bcol);                            \
        cp16s(_b + ((brow + 16) * SB_STRIDE + bcol) * 2,                           \
              (Bop) + (_k + brow + 16) * (ldB) + n0 + bcol);                       \
        asm volatile("cp.async.commit_group;");                                    \
    } while (0)

#define H_COMPUTE_SLAB(sa, sb) do {                                                \
_Pragma("unroll")                                                                  \
        for (int ks = 0; ks < 2; ks++) {                                           \
            uint32_t a[4][4], b[4][2];                                             \
_Pragma("unroll")                                                                  \
            for (int mi = 0; mi < 4; mi++) {                                       \
                uint32_t ad = (sa) + (((wm * 64 + mi * 16 + (lane & 15)) * SA_STRIDE) \
                                    + ks * 16 + (lane >> 4) * 8) * 2;              \
                LDSM4(a[mi][0], a[mi][1], a[mi][2], a[mi][3], ad);                 \
            }                                                                      \
_Pragma("unroll")                                                                  \
            for (int njp = 0; njp < 2; njp++) {                                    \
                uint32_t bd = (sb) + (((ks * 16 + (lane & 15)) * SB_STRIDE)        \
                                    + wn * 32 + njp * 16 + (lane >> 4) * 8) * 2;   \
                uint32_t r0, r1, r2, r3;                                           \
                LDSM4T(r0, r1, r2, r3, bd);                                        \
                b[2 * njp][0] = r0; b[2 * njp][1] = r1;                            \
                b[2 * njp + 1][0] = r2; b[2 * njp + 1][1] = r3;                    \
            }                                                                      \
_Pragma("unroll")                                                                  \
            for (int mi = 0; mi < 4; mi++)                                         \
_Pragma("unroll")                                                                  \
                for (int nj = 0; nj < 4; nj++)                                     \
                    HMMA(acc[mi][nj], a[mi], b[nj]);                               \
        }                                                                          \
    } while (0)

__global__ void __launch_bounds__(256, 2) k_hgemm(
    const __half* __restrict__ A, const __half* __restrict__ B, void* __restrict__ Cv,
    int K, int lda, int ldb, int ldc,
    int halfOut, int mswap) {
    extern __shared__ __align__(16) char hs[];
    const uint32_t base = smem_u32(hs);
    const int tid = threadIdx.x;
    const int wid = tid >> 5, lane = tid & 31;
    const int wm = wid & 1, wn = wid >> 1;
    const int g = lane >> 2, t4 = lane & 3;
    const int bm = mswap ? blockIdx.x : blockIdx.y;
    const int bn = mswap ? blockIdx.y : blockIdx.x;
    const int m0 = bm * 128;
    const long n0 = (long)bn * 128;
    const int KT = K >> 5;

    const int arow = tid >> 2, acol = (tid & 3) * 8;
    const int brow = tid >> 4, bcol = (tid & 15) * 8;

    float acc[4][4][4];
#pragma unroll
    for (int i = 0; i < 4; i++)
#pragma unroll
        for (int j = 0; j < 4; j++)
#pragma unroll
            for (int r = 0; r < 4; r++) acc[i][j][r] = 0.f;

#pragma unroll
    for (int s = 0; s < H_NSTG - 1; s++)
        if (s < KT) H_ISSUE_BODY(s, s, A, B, lda, ldb);
    int put = H_NSTG - 1, cur = 0;

    for (int kt = 0; kt < KT; kt++) {
        asm volatile("cp.async.wait_group %0;" :: "n"(H_NSTG - 2));
        __syncthreads();
        int nt = kt + H_NSTG - 1;
        if (nt < KT) {
            H_ISSUE_BODY(put, nt, A, B, lda, ldb);
            if (++put == H_NSTG) put = 0;
        }
        const uint32_t sa = base + cur * H_STAGE;
        const uint32_t sb = sa + SA_BYTES;
        if (++cur == H_NSTG) cur = 0;
        H_COMPUTE_SLAB(sa, sb);
    }

#pragma unroll
    for (int mi = 0; mi < 4; mi++) {
        int r = wm * 64 + mi * 16 + g;
#pragma unroll
        for (int nj = 0; nj < 4; nj++) {
            long c = wn * 32 + nj * 8 + t4 * 2;
            float v00 = acc[mi][nj][0];
            float v01 = acc[mi][nj][1];
            float v10 = acc[mi][nj][2];
            float v11 = acc[mi][nj][3];
            if (halfOut) {
                __half* Ch = (__half*)Cv;
                __half2 h0, h1;
                h0.x = __float2half(v00); h0.y = __float2half(v01);
                h1.x = __float2half(v10); h1.y = __float2half(v11);
                *(__half2*)(Ch + (long)(m0 + r) * ldc + n0 + c) = h0;
                *(__half2*)(Ch + (long)(m0 + r + 8) * ldc + n0 + c) = h1;
            } else {
                float* C = (float*)Cv;
                float2 f0, f1;
                f0.x = v00; f0.y = v01;
                f1.x = v10; f1.y = v11;
                *(float2*)(C + (long)(m0 + r) * ldc + n0 + c) = f0;
                *(float2*)(C + (long)(m0 + r + 8) * ldc + n0 + c) = f1;
            }
        }
    }
}

// merged output GEMM: z selects branch (Xr/Z2/Z3); C cols offset z*512; fp32 out + rank-1
__global__ void __launch_bounds__(256, 2) k_hgemm3(
    const __half* __restrict__ A0, const __half* __restrict__ A1h, const __half* __restrict__ A2h,
    float* __restrict__ C,
    const __half* __restrict__ B0, const __half* __restrict__ B1h, const __half* __restrict__ B2h,
    const float* __restrict__ u0, const float* __restrict__ u1v, const float* __restrict__ u2v,
    const float* __restrict__ w0, const float* __restrict__ w1v, const float* __restrict__ w2v) {
    extern __shared__ __align__(16) char hs[];
    const uint32_t base = smem_u32(hs);
    const int tid = threadIdx.x;
    const int wid = tid >> 5, lane = tid & 31;
    const int wm = wid & 1, wn = wid >> 1;
    const int g = lane >> 2, t4 = lane & 3;
    const int z = blockIdx.z;
    const __half* A = (z == 0) ? A0 : (z == 1) ? A1h : A2h;
    const __half* B = (z == 0) ? B0 : (z == 1) ? B1h : B2h;
    const float* u = (z == 0) ? u0 : (z == 1) ? u1v : u2v;
    const float* w = (z == 0) ? w0 : (z == 1) ? w1v : w2v;
    const int m0 = blockIdx.y * 128;
    const long n0 = (long)blockIdx.x * 128;
    const long cbase = (long)z * 512;
    const int KT = 512 >> 5;   // 16
    const int lda = 512, ldb = 512, ldc = 1536;

    const int arow = tid >> 2, acol = (tid & 3) * 8;
    const int brow = tid >> 4, bcol = (tid & 15) * 8;

    float acc[4][4][4];
#pragma unroll
    for (int i = 0; i < 4; i++)
#pragma unroll
        for (int j = 0; j < 4; j++)
#pragma unroll
            for (int r = 0; r < 4; r++) acc[i][j][r] = 0.f;

#pragma unroll
    for (int s = 0; s < H_NSTG - 1; s++)
        if (s < KT) H_ISSUE_BODY(s, s, A, B, lda, ldb);
    int put = H_NSTG - 1, cur = 0;

    for (int kt = 0; kt < KT; kt++) {
        asm volatile("cp.async.wait_group %0;" :: "n"(H_NSTG - 2));
        __syncthreads();
        int nt = kt + H_NSTG - 1;
        if (nt < KT) {
            H_ISSUE_BODY(put, nt, A, B, lda, ldb);
            if (++put == H_NSTG) put = 0;
        }
        const uint32_t sa = base + cur * H_STAGE;
        const uint32_t sb = sa + SA_BYTES;
        if (++cur == H_NSTG) cur = 0;
        H_COMPUTE_SLAB(sa, sb);
    }

#pragma unroll
    for (int mi = 0; mi < 4; mi++) {
        int r = wm * 64 + mi * 16 + g;
        float uu0 = u[m0 + r], uu1 = u[m0 + r + 8];
#pragma unroll
        for (int nj = 0; nj < 4; nj++) {
            long c = wn * 32 + nj * 8 + t4 * 2;
            float w0v = w[n0 + c], w1vv = w[n0 + c + 1];
            float2 f0, f1;
            f0.x = acc[mi][nj][0] + uu0 * w0v;
            f0.y = acc[mi][nj][1] + uu0 * w1vv;
            f1.x = acc[mi][nj][2] + uu1 * w0v;
            f1.y = acc[mi][nj][3] + uu1 * w1vv;
            *(float2*)(C + (long)(m0 + r) * ldc + cbase + n0 + c) = f0;
            *(float2*)(C + (long)(m0 + r + 8) * ldc + cbase + n0 + c) = f1;
        }
    }
}

// ---------------- launch ----------------
extern "C" void kernel_launch(void* const* d_in, const int* in_sizes, int n_in,
                              void* d_out, int out_size) {
    const float* X  = (const float*)d_in[0];
    const float* W1 = (const float*)d_in[1];
    const float* b1 = (const float*)d_in[2];
    const float* W2 = (const float*)d_in[3];
    const float* b2 = (const float*)d_in[4];
    const float* W3 = (const float*)d_in[5];
    const float* b3 = (const float*)d_in[6];
    float* out = (float*)d_out;

    __half *pCS, *pWINV, *pA1, *pA2, *pA3, *pYfh, *pU, *pZ2, *pZ3, *pXr;
    float *pDL, *pQ, *pu1, *pu2, *pu3, *pw1, *pw2, *pw3;
    cudaGetSymbolAddress((void**)&pCS, g_CS);
    cudaGetSymbolAddress((void**)&pWINV, g_WINV);
    cudaGetSymbolAddress((void**)&pDL, g_DL);
    cudaGetSymbolAddress((void**)&pQ, g_Q);
    cudaGetSymbolAddress((void**)&pA1, g_A1);
    cudaGetSymbolAddress((void**)&pA2, g_A2);
    cudaGetSymbolAddress((void**)&pA3, g_A3);
    cudaGetSymbolAddress((void**)&pu1, g_u1);
    cudaGetSymbolAddress((void**)&pu2, g_u2);
    cudaGetSymbolAddress((void**)&pu3, g_u3);
    cudaGetSymbolAddress((void**)&pw1, g_w1);
    cudaGetSymbolAddress((void**)&pw2, g_w2);
    cudaGetSymbolAddress((void**)&pw3, g_w3);
    cudaGetSymbolAddress((void**)&pYfh, g_Yfh);
    cudaGetSymbolAddress((void**)&pU, g_U);
    cudaGetSymbolAddress((void**)&pZ2, g_Z2);
    cudaGetSymbolAddress((void**)&pZ3, g_Z3);
    cudaGetSymbolAddress((void**)&pXr, g_Xr);

    cudaFuncSetAttribute(k_hgemm, cudaFuncAttributeMaxDynamicSharedMemorySize, H_SMEM);
    cudaFuncSetAttribute(k_hgemm3, cudaFuncAttributeMaxDynamicSharedMemorySize, H_SMEM);

    // launch order: U GEMM at position #4 so ncu (-s 5 -c 1 w/ offset) captures it
    k_build_tw<<<(MTOT * 32) / 256, 256>>>();
    k_build_cs<<<(512 * 1024) / 256, 256>>>();
    k_fold<<<dim3(4, 1024), 128>>>(X);

    // U = CS[512x2048] @ Yfh[2048x16384] -> half (mswap=1 for B-stream L2 reuse)
    k_hgemm<<<dim3(4, 128), 256, H_SMEM>>>(pCS, pYfh, pU, 2048,
                                           2048, 16384, 16384, 1, 1);
    k_fixup<<<4, 128>>>();
    k_build_dl<<<(512 * 512) / 256, 256>>>();
    k_build_u<<<MTOT / 256, 256>>>();
    k_build_w<<<4, 128>>>(512, b1, pw1);
    k_build_w<<<4, 128>>>(256, b2, pw2);
    k_build_w<<<4, 128>>>(128, b3, pw3);

    // builders (tf32): Q = Wk @ DL[0:Kk]; Ak = Q^T @ DL  (half out)
    k_mma<<<dim3(4, 4), 256>>>(W1, pDL, pQ, 512, 512, 512, 512, 512, 512, 0, 0);
    k_mma<<<dim3(4, 4), 256>>>(pQ, pDL, pA1, 512, 512, 512, 512, 512, 512, 1, 1);
    k_mma<<<dim3(4, 2), 256>>>(W2, pDL, pQ, 256, 512, 256, 256, 512, 512, 0, 0);
    k_mma<<<dim3(4, 4), 256>>>(pQ, pDL, pA2, 512, 512, 256, 512, 512, 512, 1, 1);
    k_mma<<<dim3(4, 1), 256>>>(W3, pDL, pQ, 128, 512, 128, 128, 512, 512, 0, 0);
    k_mma<<<dim3(4, 4), 256>>>(pQ, pDL, pA3, 512, 512, 128, 512, 512, 512, 1, 1);

    // V = WINV[2048x512] @ U[512x16384] -> fp16, written into Yfh (dead after U)
    k_hgemm<<<dim3(128, 16), 256, H_SMEM>>>(pWINV, pU, pYfh, 512,
                                            512, 16384, 16384, 1, 0);
    k_combine<<<dim3(4, 1024), 128>>>(pYfh);

    // merged outputs: z=0 Xr@A1, z=1 Z2@A2, z=2 Z3@A3; C col offset z*512
    k_hgemm3<<<dim3(4, 256, 3), 256, H_SMEM>>>(pXr, pZ2, pZ3, out,
                                               pA1, pA2, pA3,
                                               pu1, pu2, pu3,
                                               pw1, pw2, pw3);
    (void)in_sizes; (void)n_in; (void)out_size;
}

// round 17
// speedup vs baseline: 1.1529x; 1.0015x over previous
#include <cuda_runtime.h>
#include <cuda_fp16.h>
#include <math.h>
#include <stdint.h>

#define MTOT 32768
#define LDIM 512

// ---------------- scratch (device globals; allocation-free) ----------------
__device__ __align__(128) float  g_TW[MTOT * 32 * 2];
__device__ __align__(128) __half g_CS[512 * 2048];
__device__ __align__(128) __half g_WINV[2048 * 512];   // cos/sin, NO 2/M scale
__device__ __align__(128) float  g_DL[512 * 512];
__device__ __align__(128) float  g_Q[512 * 512];
__device__ __align__(128) __half g_A1[512 * 512];
__device__ __align__(128) __half g_A2[512 * 512];
__device__ __align__(128) __half g_A3[512 * 512];
__device__ __align__(128) float  g_u1[MTOT];
__device__ __align__(128) float  g_u2[MTOT];
__device__ __align__(128) float  g_u3[MTOT];
__device__ __align__(128) float  g_w1[512];
__device__ __align__(128) float  g_w2[512];
__device__ __align__(128) float  g_w3[512];
__device__ __align__(128) __half g_Yfh[2048 * 16384];  // fold output; REUSED as V (fp16)
__device__ __align__(128) __half g_U[512 * 16384];     // U (fp16)
__device__ __align__(128) __half g_Z2[MTOT * 512];
__device__ __align__(128) __half g_Z3[MTOT * 512];
__device__ __align__(128) __half g_Xr[MTOT * 512];

__device__ __forceinline__ uint32_t f2tf(float x) {
    uint32_t r;
    asm("cvt.rna.tf32.f32 %0, %1;" : "=r"(r) : "f"(x));
    return r;
}

__device__ __forceinline__ uint32_t smem_u32(const void* p) {
    uint32_t a;
    asm("{ .reg .u64 t; cvta.to.shared.u64 t, %1; cvt.u32.u64 %0, t; }" : "=r"(a) : "l"(p));
    return a;
}
__device__ __forceinline__ void cp16s(uint32_t saddr, const void* g) {
    asm volatile("cp.async.cg.shared.global [%0], [%1], 16;" :: "r"(saddr), "l"(g));
}
#define LDSM4(r0, r1, r2, r3, a)                                                   \
    asm volatile("ldmatrix.sync.aligned.m8n8.x4.shared.b16 {%0,%1,%2,%3}, [%4];"   \
                 : "=r"(r0), "=r"(r1), "=r"(r2), "=r"(r3) : "r"(a))
#define LDSM4T(r0, r1, r2, r3, a)                                                  \
    asm volatile("ldmatrix.sync.aligned.m8n8.x4.trans.shared.b16 {%0,%1,%2,%3}, [%4];" \
                 : "=r"(r0), "=r"(r1), "=r"(r2), "=r"(r3) : "r"(a))
#define HMMA(c, a, b)                                                              \
    asm volatile("mma.sync.aligned.m16n8k16.row.col.f32.f16.f16.f32 "              \
                 "{%0,%1,%2,%3}, {%4,%5,%6,%7}, {%8,%9}, {%0,%1,%2,%3};"           \
                 : "+f"((c)[0]), "+f"((c)[1]), "+f"((c)[2]), "+f"((c)[3])          \
                 : "r"((a)[0]), "r"((a)[1]), "r"((a)[2]), "r"((a)[3]),             \
                   "r"((b)[0]), "r"((b)[1]))

// ---------------- table builders ----------------
__global__ void k_build_tw() {
    int id = blockIdx.x * 256 + threadIdx.x;
    if (id >= MTOT * 32) return;
    int n = id >> 5, t = id & 31;
    int mm = ((2 * n + 1) * t) & 131071;
    float sn, cs;
    sincospif((float)mm * (1.0f / 65536.0f), &sn, &cs);
    g_TW[2 * id + 0] = cs;
    g_TW[2 * id + 1] = sn;
}

__global__ void k_build_cs() {
    int id = blockIdx.x * 256 + threadIdx.x;
    if (id >= 512 * 1024) return;
    int j = id >> 10, p = id & 1023;
    int mm = (j * (2 * p + 1)) & 2047;
    float sn, cs;
    sincospif((float)mm * (1.0f / 1024.0f), &sn, &cs);
    g_CS[j * 2048 + p] = __float2half(cs);
    g_CS[j * 2048 + 1024 + p] = __float2half(-sn);
    g_WINV[p * 512 + j] = __float2half(cs);
    g_WINV[(1024 + p) * 512 + j] = __float2half(sn);
}

__global__ void k_build_dl() {
    int id = blockIdx.x * 256 + threadIdx.x;
    if (id >= 512 * 512) return;
    int k = id >> 9, n = id & 511;
    int mm = (k * (2 * n + 1)) & 2047;
    float cs = cospif((float)mm * (1.0f / 1024.0f));
    float ck = (k == 0) ? 0.04419417382415922f : 0.0625f;
    g_DL[id] = ck * cs;
}

struct C2d { double x, y; };
__device__ __forceinline__ C2d cdiv(C2d a, C2d b) {
    double d = b.x * b.x + b.y * b.y;
    C2d r; r.x = (a.x * b.x + a.y * b.y) / d; r.y = (a.y * b.x - a.x * b.y) / d; return r;
}
__device__ __forceinline__ C2d cmul(C2d a, C2d b) {
    C2d r; r.x = a.x * b.x - a.y * b.y; r.y = a.x * b.y + a.y * b.x; return r;
}
__global__ void k_build_u() {
    int n = blockIdx.x * 256 + threadIdx.x;
    if (n >= MTOT) return;
    long on = 2L * n + 1;
    double s1, c1, s64, c64, s32, c32, s16, c16;
    sincospi((double)on / 65536.0, &s1, &c1);
    sincospi((double)(on & 2047) / 1024.0, &s64, &c64);
    sincospi((double)(on & 4095) / 2048.0, &s32, &c32);
    sincospi((double)(on & 8191) / 4096.0, &s16, &c16);
    C2d numer; numer.x = 1.0; numer.y = (n & 1) ? 1.0 : -1.0;
    C2d d1;  d1.x  = 1.0 - c1;  d1.y  = -s1;
    C2d d64; d64.x = 1.0 - c64; d64.y = -s64;
    C2d n32; n32.x = 1.0 - c32; n32.y = -s32;
    C2d n16; n16.x = 1.0 - c16; n16.y = -s16;
    double F1 = cdiv(numer, d1).x;
    C2d g = cdiv(numer, d64);
    double F2 = cmul(g, cdiv(n32, d1)).x;
    double F3 = cmul(g, cdiv(n16, d1)).x;
    const double C2M = 0.0078125;
    const double C1M = 0.005524271728019903;
    g_u1[n] = (float)(C2M * (F1 - 1.0) + C1M);
    g_u2[n] = (float)(C2M * (F2 - 1.0) + C1M);
    g_u3[n] = (float)(C2M * (F3 - 1.0) + C1M);
}

__global__ void k_build_w(int Kb, const float* __restrict__ b, float* __restrict__ w) {
    int c = blockIdx.x * 128 + threadIdx.x;
    if (c >= 512) return;
    float s = 0.f;
    for (int k = 0; k < Kb; k++) s += g_DL[k * 512 + c] * b[k];
    w[c] = s;
}

// ---------------- fold: X -> Yfh (fp16) + Xr (fp16) ----------------
__global__ void __launch_bounds__(128) k_fold(const float* __restrict__ X) {
    const int p = blockIdx.y;
    const int l = blockIdx.x * 128 + threadIdx.x;
    __shared__ float tw[32][64];
    for (int i = threadIdx.x; i < 2048; i += 128) {
        int q = i >> 6;
        tw[q][i & 63] = g_TW[(((long)(q << 10) + p)) * 64 + (i & 63)];
    }
    __syncthreads();
    float c[32], s[32];
#pragma unroll
    for (int t = 0; t < 32; t++) { c[t] = 0.f; s[t] = 0.f; }
    for (int q = 0; q < 32; q++) {
        int n = (q << 10) + p;
        float x = X[(long)n * 512 + l];
        g_Xr[(long)n * 512 + l] = __float2half(x);
#pragma unroll
        for (int t = 0; t < 32; t++) {
            c[t] += tw[q][2 * t] * x;
            s[t] += tw[q][2 * t + 1] * x;
        }
    }
#pragma unroll
    for (int t = 0; t < 32; t++) {
        g_Yfh[(long)p * 16384 + t * 512 + l] = __float2half(c[t]);
        g_Yfh[(long)(1024 + p) * 16384 + t * 512 + l] = __float2half(s[t]);
    }
}

// halve k=0 entries: U row j=0, first 512 cols (t=0)
__global__ void k_fixup() {
    int l = blockIdx.x * 128 + threadIdx.x;
    if (l < 512) g_U[l] = __float2half(__half2float(g_U[l]) * 0.5f);
}

// ---------------- combine: V (fp16) -> Z3 (t<16), Z2 (t<32); applies 2/M ----------------
__global__ void __launch_bounds__(128) k_combine(const __half* __restrict__ V) {
    const int p = blockIdx.y;
    const int l = blockIdx.x * 128 + threadIdx.x;
    __shared__ float tw[32][64];
    for (int i = threadIdx.x; i < 2048; i += 128) {
        int q = i >> 6;
        tw[q][i & 63] = g_TW[(((long)(q << 10) + p)) * 64 + (i & 63)];
    }
    __syncthreads();
    float vc[32], vs[32];
#pragma unroll
    for (int t = 0; t < 32; t++) {
        vc[t] = __half2float(V[(long)p * 16384 + t * 512 + l]);
        vs[t] = __half2float(V[(long)(1024 + p) * 16384 + t * 512 + l]);
    }
    const float SC = 2.0f / 32768.0f;
    for (int q = 0; q < 32; q++) {
        float acc = 0.f;
#pragma unroll
        for (int t = 0; t < 16; t++) acc += tw[q][2 * t] * vc[t] - tw[q][2 * t + 1] * vs[t];
        int n = (q << 10) + p;
        g_Z3[(long)n * 512 + l] = __float2half(acc * SC);
#pragma unroll
        for (int t = 16; t < 32; t++) acc += tw[q][2 * t] * vc[t] - tw[q][2 * t + 1] * vs[t];
        g_Z2[(long)n * 512 + l] = __float2half(acc * SC);
    }
}

// ---------------- small tf32 mma.sync GEMM (builder matrices) ----------------
__global__ void __launch_bounds__(256) k_mma(
    const float* __restrict__ A, const float* __restrict__ B, void* __restrict__ Cv,
    int M, int N, int K, int lda, int ldb, int ldc, int transA, int halfOut) {
    __shared__ uint32_t As[16][132];
    __shared__ uint32_t Bs[16][132];
    const int tid = threadIdx.x;
    const int wid = tid >> 5, lane = tid & 31;
    const int wm = wid & 1, wn = wid >> 1;
    const int g = lane >> 2, t4 = lane & 3;
    const int m0 = blockIdx.y * 128, n0 = blockIdx.x * 128;
    float acc[4][4][4];
#pragma unroll
    for (int i = 0; i < 4; i++)
#pragma unroll
        for (int j = 0; j < 4; j++)
#pragma unroll
            for (int r = 0; r < 4; r++) acc[i][j][r] = 0.f;
    const int bk = tid >> 4, bn = (tid & 15) * 8;
    const int ar = tid >> 1, ak = (tid & 1) * 8;
    for (int k0 = 0; k0 < K; k0 += 16) {
        const float* Ap;
        if (transA) Ap = A + (long)(k0 + bk) * lda + m0 + bn;
        else        Ap = A + (long)(m0 + ar) * lda + k0 + ak;
        float4 pa0 = *(const float4*)(Ap);
        float4 pa1 = *(const float4*)(Ap + 4);
        const float* Bp = B + (long)(k0 + bk) * ldb + n0 + bn;
        float4 pb0 = *(const float4*)(Bp);
        float4 pb1 = *(const float4*)(Bp + 4);
        if (transA) {
            uint4 v0, v1;
            v0.x = f2tf(pa0.x); v0.y = f2tf(pa0.y); v0.z = f2tf(pa0.z); v0.w = f2tf(pa0.w);
            v1.x = f2tf(pa1.x); v1.y = f2tf(pa1.y); v1.z = f2tf(pa1.z); v1.w = f2tf(pa1.w);
            *(uint4*)&As[bk][bn] = v0;
            *(uint4*)&As[bk][bn + 4] = v1;
        } else {
            As[ak + 0][ar] = f2tf(pa0.x);
            As[ak + 1][ar] = f2tf(pa0.y);
            As[ak + 2][ar] = f2tf(pa0.z);
            As[ak + 3][ar] = f2tf(pa0.w);
            As[ak + 4][ar] = f2tf(pa1.x);
            As[ak + 5][ar] = f2tf(pa1.y);
            As[ak + 6][ar] = f2tf(pa1.z);
            As[ak + 7][ar] = f2tf(pa1.w);
        }
        {
            uint4 v0, v1;
            v0.x = f2tf(pb0.x); v0.y = f2tf(pb0.y); v0.z = f2tf(pb0.z); v0.w = f2tf(pb0.w);
            v1.x = f2tf(pb1.x); v1.y = f2tf(pb1.y); v1.z = f2tf(pb1.z); v1.w = f2tf(pb1.w);
            *(uint4*)&Bs[bk][bn] = v0;
            *(uint4*)&Bs[bk][bn + 4] = v1;
        }
        __syncthreads();
#pragma unroll
        for (int ks = 0; ks < 2; ks++) {
            const int kb = ks * 8;
            uint32_t a[4][4], b[4][2];
#pragma unroll
            for (int mi = 0; mi < 4; mi++) {
                int row = wm * 64 + mi * 16 + g;
                a[mi][0] = As[kb + t4][row];
                a[mi][1] = As[kb + t4][row + 8];
                a[mi][2] = As[kb + t4 + 4][row];
                a[mi][3] = As[kb + t4 + 4][row + 8];
            }
#pragma unroll
            for (int nj = 0; nj < 4; nj++) {
                int col = wn * 32 + nj * 8 + g;
                b[nj][0] = Bs[kb + t4][col];
                b[nj][1] = Bs[kb + t4 + 4][col];
            }
#pragma unroll
            for (int mi = 0; mi < 4; mi++)
#pragma unroll
                for (int nj = 0; nj < 4; nj++) {
                    asm("mma.sync.aligned.m16n8k8.row.col.f32.tf32.tf32.f32 "
                        "{%0,%1,%2,%3}, {%4,%5,%6,%7}, {%8,%9}, {%0,%1,%2,%3};"
                        : "+f"(acc[mi][nj][0]), "+f"(acc[mi][nj][1]),
                          "+f"(acc[mi][nj][2]), "+f"(acc[mi][nj][3])
                        : "r"(a[mi][0]), "r"(a[mi][1]), "r"(a[mi][2]), "r"(a[mi][3]),
                          "r"(b[nj][0]), "r"(b[nj][1]));
                }
        }
        __syncthreads();
    }
#pragma unroll
    for (int mi = 0; mi < 4; mi++) {
        int r = wm * 64 + mi * 16 + g;
#pragma unroll
        for (int nj = 0; nj < 4; nj++) {
            int c = wn * 32 + nj * 8 + t4 * 2;
            if (halfOut) {
                __half* Ch = (__half*)Cv;
                __half2 h0, h1;
                h0.x = __float2half(acc[mi][nj][0]); h0.y = __float2half(acc[mi][nj][1]);
                h1.x = __float2half(acc[mi][nj][2]); h1.y = __float2half(acc[mi][nj][3]);
                *(__half2*)(Ch + (long)(m0 + r) * ldc + n0 + c) = h0;
                *(__half2*)(Ch + (long)(m0 + r + 8) * ldc + n0 + c) = h1;
            } else {
                float* C = (float*)Cv;
                float2 v0, v1;
                v0.x = acc[mi][nj][0]; v0.y = acc[mi][nj][1];
                v1.x = acc[mi][nj][2]; v1.y = acc[mi][nj][3];
                *(float2*)(C + (long)(m0 + r) * ldc + n0 + c) = v0;
                *(float2*)(C + (long)(m0 + r + 8) * ldc + n0 + c) = v1;
            }
        }
    }
}

// ---------------- pipelined fp16 GEMM (LDSM + HMMA), 128x128, warp 64x32 ----------------
// BK=64 halves, 3-stage cp.async, 1 sync/slab.
#define SA_STRIDE 72     // halves per A row (144B; 16*r mod 128 distinct per ldsm phase)
#define SB_STRIDE 136    // halves per B row (272B)
#define SA_BYTES (128 * SA_STRIDE * 2)   // 18432
#define SB_BYTES (64 * SB_STRIDE * 2)    // 17408
#define H_STAGE (SA_BYTES + SB_BYTES)    // 35840
#define H_NSTG 3
#define H_SMEM (H_NSTG * H_STAGE)        // 107520 (x2 CTA = 215KB < 228KB)

// shared k-loop body between k_hgemm and k_hgemm3
#define H_ISSUE_BODY(st, kt, Aop, Bop, ldA, ldB) do {                              \
        uint32_t _a = base + (st) * H_STAGE;                                       \
        uint32_t _b = _a + SA_BYTES;                                               \
        long _k = (long)(kt) << 6;                                                 \
        cp16s(_a + (arow * SA_STRIDE + acol) * 2,                                  \
              (Aop) + (long)(m0 + arow) * (ldA) + _k + acol);                      \
        cp16s(_a + ((arow + 32) * SA_STRIDE + acol) * 2,                           \
              (Aop) + (long)(m0 + arow + 32) * (ldA) + _k + acol);                 \
        cp16s(_a + ((arow + 64) * SA_STRIDE + acol) * 2,                           \
              (Aop) + (long)(m0 + arow + 64) * (ldA) + _k + acol);                 \
        cp16s(_a + ((arow + 96) * SA_STRIDE + acol) * 2,                           \
              (Aop) + (long)(m0 + arow + 96) * (ldA) + _k + acol);                 \
        cp16s(_b + (brow * SB_STRIDE + bcol) * 2,                                  \
              (Bop) + (_k + brow) * (ldB) + n0 + bcol);                            \
        cp16s(_b + ((brow + 16) * SB_STRIDE + bcol) * 2,                           \
              (Bop) + (_k + brow + 16) * (ldB) + n0 + bcol);                       \
        cp16s(_b + ((brow + 32) * SB_STRIDE + bcol) * 2,                           \
              (Bop) + (_k + brow + 32) * (ldB) + n0 + bcol);                       \
        cp16s(_b + ((brow + 48) * SB_STRIDE + bcol) * 2,                           \
              (Bop) + (_k + brow + 48) * (ldB) + n0 + bcol);                       \
        asm volatile("cp.async.commit_group;");                                    \
    } while (0)

#define H_COMPUTE_SLAB(sa, sb) do {                                                \
_Pragma("unroll")                                                                  \
        for (int ks = 0; ks < 4; ks++) {                                           \
            uint32_t a[4][4], b[4][2];                                             \
_Pragma("unroll")                                                                  \
            for (int mi = 0; mi < 4; mi++) {                                       \
                uint32_t ad = (sa) + (((wm * 64 + mi * 16 + (lane & 15)) * SA_STRIDE) \
                                    + ks * 16 + (lane >> 4) * 8) * 2;              \
                LDSM4(a[mi][0], a[mi][1], a[mi][2], a[mi][3], ad);                 \
            }                                                                      \
_Pragma("unroll")                                                                  \
            for (int njp = 0; njp < 2; njp++) {                                    \
                uint32_t bd = (sb) + (((ks * 16 + (lane & 15)) * SB_STRIDE)        \
                                    + wn * 32 + njp * 16 + (lane >> 4) * 8) * 2;   \
                uint32_t r0, r1, r2, r3;                                           \
                LDSM4T(r0, r1, r2, r3, bd);                                        \
                b[2 * njp][0] = r0; b[2 * njp][1] = r1;                            \
                b[2 * njp + 1][0] = r2; b[2 * njp + 1][1] = r3;                    \
            }                                                                      \
_Pragma("unroll")                                                                  \
            for (int mi = 0; mi < 4; mi++)                                         \
_Pragma("unroll")                                                                  \
                for (int nj = 0; nj < 4; nj++)                                     \
                    HMMA(acc[mi][nj], a[mi], b[nj]);                               \
        }                                                                          \
    } while (0)

__global__ void __launch_bounds__(256, 2) k_hgemm(
    const __half* __restrict__ A, const __half* __restrict__ B, void* __restrict__ Cv,
    int K, int lda, int ldb, int ldc,
    int halfOut, int mswap) {
    extern __shared__ __align__(16) char hs[];
    const uint32_t base = smem_u32(hs);
    const int tid = threadIdx.x;
    const int wid = tid >> 5, lane = tid & 31;
    const int wm = wid & 1, wn = wid >> 1;
    const int g = lane >> 2, t4 = lane & 3;
    const int bm = mswap ? blockIdx.x : blockIdx.y;
    const int bn = mswap ? blockIdx.y : blockIdx.x;
    const int m0 = bm * 128;
    const long n0 = (long)bn * 128;
    const int KT = K >> 6;

    const int arow = tid >> 3, acol = (tid & 7) * 8;   // A: 4 chunks (rows +0,+32,+64,+96)
    const int brow = tid >> 4, bcol = (tid & 15) * 8;  // B: 4 chunks (k +0,+16,+32,+48)

    float acc[4][4][4];
#pragma unroll
    for (int i = 0; i < 4; i++)
#pragma unroll
        for (int j = 0; j < 4; j++)
#pragma unroll
            for (int r = 0; r < 4; r++) acc[i][j][r] = 0.f;

#pragma unroll
    for (int s = 0; s < H_NSTG - 1; s++)
        if (s < KT) H_ISSUE_BODY(s, s, A, B, lda, ldb);
    int put = H_NSTG - 1, cur = 0;

    for (int kt = 0; kt < KT; kt++) {
        asm volatile("cp.async.wait_group %0;" :: "n"(H_NSTG - 2));
        __syncthreads();
        int nt = kt + H_NSTG - 1;
        if (nt < KT) {
            H_ISSUE_BODY(put, nt, A, B, lda, ldb);
            if (++put == H_NSTG) put = 0;
        }
        const uint32_t sa = base + cur * H_STAGE;
        const uint32_t sb = sa + SA_BYTES;
        if (++cur == H_NSTG) cur = 0;
        H_COMPUTE_SLAB(sa, sb);
    }

#pragma unroll
    for (int mi = 0; mi < 4; mi++) {
        int r = wm * 64 + mi * 16 + g;
#pragma unroll
        for (int nj = 0; nj < 4; nj++) {
            long c = wn * 32 + nj * 8 + t4 * 2;
            float v00 = acc[mi][nj][0];
            float v01 = acc[mi][nj][1];
            float v10 = acc[mi][nj][2];
            float v11 = acc[mi][nj][3];
            if (halfOut) {
                __half* Ch = (__half*)Cv;
                __half2 h0, h1;
                h0.x = __float2half(v00); h0.y = __float2half(v01);
                h1.x = __float2half(v10); h1.y = __float2half(v11);
                *(__half2*)(Ch + (long)(m0 + r) * ldc + n0 + c) = h0;
                *(__half2*)(Ch + (long)(m0 + r + 8) * ldc + n0 + c) = h1;
            } else {
                float* C = (float*)Cv;
                float2 f0, f1;
                f0.x = v00; f0.y = v01;
                f1.x = v10; f1.y = v11;
                *(float2*)(C + (long)(m0 + r) * ldc + n0 + c) = f0;
                *(float2*)(C + (long)(m0 + r + 8) * ldc + n0 + c) = f1;
            }
        }
    }
}

// merged output GEMM: z selects branch (Xr/Z2/Z3); C cols offset z*512; fp32 out + rank-1
__global__ void __launch_bounds__(256, 2) k_hgemm3(
    const __half* __restrict__ A0, const __half* __restrict__ A1h, const __half* __restrict__ A2h,
    float* __restrict__ C,
    const __half* __restrict__ B0, const __half* __restrict__ B1h, const __half* __restrict__ B2h,
    const float* __restrict__ u0, const float* __restrict__ u1v, const float* __restrict__ u2v,
    const float* __restrict__ w0, const float* __restrict__ w1v, const float* __restrict__ w2v) {
    extern __shared__ __align__(16) char hs[];
    const uint32_t base = smem_u32(hs);
    const int tid = threadIdx.x;
    const int wid = tid >> 5, lane = tid & 31;
    const int wm = wid & 1, wn = wid >> 1;
    const int g = lane >> 2, t4 = lane & 3;
    const int z = blockIdx.z;
    const __half* A = (z == 0) ? A0 : (z == 1) ? A1h : A2h;
    const __half* B = (z == 0) ? B0 : (z == 1) ? B1h : B2h;
    const float* u = (z == 0) ? u0 : (z == 1) ? u1v : u2v;
    const float* w = (z == 0) ? w0 : (z == 1) ? w1v : w2v;
    const int m0 = blockIdx.y * 128;
    const long n0 = (long)blockIdx.x * 128;
    const long cbase = (long)z * 512;
    const int KT = 512 >> 6;   // 8
    const int lda = 512, ldb = 512, ldc = 1536;

    const int arow = tid >> 3, acol = (tid & 7) * 8;
    const int brow = tid >> 4, bcol = (tid & 15) * 8;

    float acc[4][4][4];
#pragma unroll
    for (int i = 0; i < 4; i++)
#pragma unroll
        for (int j = 0; j < 4; j++)
#pragma unroll
            for (int r = 0; r < 4; r++) acc[i][j][r] = 0.f;

#pragma unroll
    for (int s = 0; s < H_NSTG - 1; s++)
        if (s < KT) H_ISSUE_BODY(s, s, A, B, lda, ldb);
    int put = H_NSTG - 1, cur = 0;

    for (int kt = 0; kt < KT; kt++) {
        asm volatile("cp.async.wait_group %0;" :: "n"(H_NSTG - 2));
        __syncthreads();
        int nt = kt + H_NSTG - 1;
        if (nt < KT) {
            H_ISSUE_BODY(put, nt, A, B, lda, ldb);
            if (++put == H_NSTG) put = 0;
        }
        const uint32_t sa = base + cur * H_STAGE;
        const uint32_t sb = sa + SA_BYTES;
        if (++cur == H_NSTG) cur = 0;
        H_COMPUTE_SLAB(sa, sb);
    }

#pragma unroll
    for (int mi = 0; mi < 4; mi++) {
        int r = wm * 64 + mi * 16 + g;
        float uu0 = u[m0 + r], uu1 = u[m0 + r + 8];
#pragma unroll
        for (int nj = 0; nj < 4; nj++) {
            long c = wn * 32 + nj * 8 + t4 * 2;
            float w0v = w[n0 + c], w1vv = w[n0 + c + 1];
            float2 f0, f1;
            f0.x = acc[mi][nj][0] + uu0 * w0v;
            f0.y = acc[mi][nj][1] + uu0 * w1vv;
            f1.x = acc[mi][nj][2] + uu1 * w0v;
            f1.y = acc[mi][nj][3] + uu1 * w1vv;
            *(float2*)(C + (long)(m0 + r) * ldc + cbase + n0 + c) = f0;
            *(float2*)(C + (long)(m0 + r + 8) * ldc + cbase + n0 + c) = f1;
        }
    }
}

// ---------------- launch ----------------
extern "C" void kernel_launch(void* const* d_in, const int* in_sizes, int n_in,
                              void* d_out, int out_size) {
    const float* X  = (const float*)d_in[0];
    const float* W1 = (const float*)d_in[1];
    const float* b1 = (const float*)d_in[2];
    const float* W2 = (const float*)d_in[3];
    const float* b2 = (const float*)d_in[4];
    const float* W3 = (const float*)d_in[5];
    const float* b3 = (const float*)d_in[6];
    float* out = (float*)d_out;

    __half *pCS, *pWINV, *pA1, *pA2, *pA3, *pYfh, *pU, *pZ2, *pZ3, *pXr;
    float *pDL, *pQ, *pu1, *pu2, *pu3, *pw1, *pw2, *pw3;
    cudaGetSymbolAddress((void**)&pCS, g_CS);
    cudaGetSymbolAddress((void**)&pWINV, g_WINV);
    cudaGetSymbolAddress((void**)&pDL, g_DL);
    cudaGetSymbolAddress((void**)&pQ, g_Q);
    cudaGetSymbolAddress((void**)&pA1, g_A1);
    cudaGetSymbolAddress((void**)&pA2, g_A2);
    cudaGetSymbolAddress((void**)&pA3, g_A3);
    cudaGetSymbolAddress((void**)&pu1, g_u1);
    cudaGetSymbolAddress((void**)&pu2, g_u2);
    cudaGetSymbolAddress((void**)&pu3, g_u3);
    cudaGetSymbolAddress((void**)&pw1, g_w1);
    cudaGetSymbolAddress((void**)&pw2, g_w2);
    cudaGetSymbolAddress((void**)&pw3, g_w3);
    cudaGetSymbolAddress((void**)&pYfh, g_Yfh);
    cudaGetSymbolAddress((void**)&pU, g_U);
    cudaGetSymbolAddress((void**)&pZ2, g_Z2);
    cudaGetSymbolAddress((void**)&pZ3, g_Z3);
    cudaGetSymbolAddress((void**)&pXr, g_Xr);

    cudaFuncSetAttribute(k_hgemm, cudaFuncAttributeMaxDynamicSharedMemorySize, H_SMEM);
    cudaFuncSetAttribute(k_hgemm3, cudaFuncAttributeMaxDynamicSharedMemorySize, H_SMEM);

    // launch order: U GEMM at position #4 so ncu (-s 5 -c 1 w/ offset) captures it
    k_build_tw<<<(MTOT * 32) / 256, 256>>>();
    k_build_cs<<<(512 * 1024) / 256, 256>>>();
    k_fold<<<dim3(4, 1024), 128>>>(X);

    // U = CS[512x2048] @ Yfh[2048x16384] -> half (mswap=1 for B-stream L2 reuse)
    k_hgemm<<<dim3(4, 128), 256, H_SMEM>>>(pCS, pYfh, pU, 2048,
                                           2048, 16384, 16384, 1, 1);
    k_fixup<<<4, 128>>>();
    k_build_dl<<<(512 * 512) / 256, 256>>>();
    k_build_u<<<MTOT / 256, 256>>>();
    k_build_w<<<4, 128>>>(512, b1, pw1);
    k_build_w<<<4, 128>>>(256, b2, pw2);
    k_build_w<<<4, 128>>>(128, b3, pw3);

    // builders (tf32): Q = Wk @ DL[0:Kk]; Ak = Q^T @ DL  (half out)
    k_mma<<<dim3(4, 4), 256>>>(W1, pDL, pQ, 512, 512, 512, 512, 512, 512, 0, 0);
    k_mma<<<dim3(4, 4), 256>>>(pQ, pDL, pA1, 512, 512, 512, 512, 512, 512, 1, 1);
    k_mma<<<dim3(4, 2), 256>>>(W2, pDL, pQ, 256, 512, 256, 256, 512, 512, 0, 0);
    k_mma<<<dim3(4, 4), 256>>>(pQ, pDL, pA2, 512, 512, 256, 512, 512, 512, 1, 1);
    k_mma<<<dim3(4, 1), 256>>>(W3, pDL, pQ, 128, 512, 128, 128, 512, 512, 0, 0);
    k_mma<<<dim3(4, 4), 256>>>(pQ, pDL, pA3, 512, 512, 128, 512, 512, 512, 1, 1);

    // V = WINV[2048x512] @ U[512x16384] -> fp16, written into Yfh (dead after U)
    k_hgemm<<<dim3(128, 16), 256, H_SMEM>>>(pWINV, pU, pYfh, 512,
                                            512, 16384, 16384, 1, 0);
    k_combine<<<dim3(4, 1024), 128>>>(pYfh);

    // merged outputs: z=0 Xr@A1, z=1 Z2@A2, z=2 Z3@A3; C col offset z*512
    k_hgemm3<<<dim3(4, 256, 3), 256, H_SMEM>>>(pXr, pZ2, pZ3, out,
                                               pA1, pA2, pA3,
                                               pu1, pu2, pu3,
                                               pw1, pw2, pw3);
    (void)in_sizes; (void)n_in; (void)out_size;
}